// round 10
// baseline (speedup 1.0000x reference)
#include <cuda_runtime.h>
#include <cstdint>

#define BB   4
#define SS   1568
#define DD   1024
#define HH   16
#define HDIM 64
#define MTOT (BB*SS)          // 6272

#define QT 64                 // query tile (attention)
#define KT 32                 // key/value tile
#define QPITCH (HDIM+4)
#define PPITCH (KT+4)

// -------- scratch (no allocation allowed; __device__ globals) --------
__device__ float g_q[BB*HH*SS*HDIM];
__device__ float g_k[BB*HH*SS*HDIM];
__device__ float g_v[BB*HH*SS*HDIM];
__device__ float g_ctx[MTOT*DD];

// ============================================================================
// tf32 helpers (sm_80-class PTX — compiles under compute_103)
// ============================================================================
__device__ __forceinline__ uint32_t f2tf(float f) {
    uint32_t u;
    asm("cvt.rna.tf32.f32 %0, %1;" : "=r"(u) : "f"(f));
    return u;
}

#define MMA_TF32(c, a, b) \
    asm volatile("mma.sync.aligned.m16n8k8.row.col.f32.tf32.tf32.f32 " \
        "{%0,%1,%2,%3}, {%4,%5,%6,%7}, {%8,%9}, {%0,%1,%2,%3};" \
        : "+f"((c)[0]), "+f"((c)[1]), "+f"((c)[2]), "+f"((c)[3]) \
        : "r"((a)[0]), "r"((a)[1]), "r"((a)[2]), "r"((a)[3]), \
          "r"((b)[0]), "r"((b)[1]))

// ============================================================================
// tf32 tensor-core GEMM: C[m,n] = sum_k A[m,k]*W[n,k] + bias[n]
// BM=128, BN=64, BK=32. 256 threads = 8 warps (4M x 2N), warp tile 32x64? no:
// warp tile 32(M) x 32(N): 2 m16-tiles x 4 n8-tiles per k8-step.
// Smem: XOR-swizzled (pk = k ^ ((row&7)<<2)), stride 32, conflict-free.
//   mode 0/1/2: A = Ain, write g_q/g_k/g_v in [B,H,S,HD]
//   mode 3:     A = g_ctx, write outp [M,D]
// ============================================================================
#define NCHUNK 32   // 1024 / 32

__global__ void __launch_bounds__(256, 2) gemm_tf32(
    const float* __restrict__ Ain, const float* __restrict__ W,
    const float* __restrict__ bias, float* __restrict__ outp, int mode)
{
    __shared__ __align__(16) uint32_t As[2][128 * 32];  // 32 KB
    __shared__ __align__(16) uint32_t Bs[2][64 * 32];   // 16 KB

    const float* A = (mode == 3) ? g_ctx : Ain;
    const int tid = threadIdx.x;
    const int wid = tid >> 5;
    const int lid = tid & 31;
    const int wm  = wid >> 1;          // 0..3  -> m offset wm*32
    const int wn  = wid & 1;           // 0..1  -> n offset wn*32
    const int g   = lid >> 2;          // 0..7
    const int t   = lid & 3;           // 0..3

    const int m0 = blockIdx.y * 128;
    const int n0 = blockIdx.x * 64;

    const float* aP = A + (size_t)m0 * DD;
    const float* wP = W + (size_t)n0 * DD;

    float acc[2][4][4];
#pragma unroll
    for (int mt = 0; mt < 2; mt++)
#pragma unroll
        for (int nt = 0; nt < 4; nt++)
#pragma unroll
            for (int j = 0; j < 4; j++) acc[mt][nt][j] = 0.f;

    float4 stA[4], stB[2];

#define LDG_CHUNK(kc) do { \
    _Pragma("unroll") \
    for (int _i = 0; _i < 4; _i++) { \
        int _idx = tid + _i * 256; \
        int _r = _idx >> 3, _c4 = _idx & 7; \
        stA[_i] = *(const float4*)(aP + (size_t)_r * DD + (kc) * 32 + _c4 * 4); \
    } \
    _Pragma("unroll") \
    for (int _i = 0; _i < 2; _i++) { \
        int _idx = tid + _i * 256; \
        int _r = _idx >> 3, _c4 = _idx & 7; \
        stB[_i] = *(const float4*)(wP + (size_t)_r * DD + (kc) * 32 + _c4 * 4); \
    } \
} while (0)

#define STS_CHUNK(buf) do { \
    _Pragma("unroll") \
    for (int _i = 0; _i < 4; _i++) { \
        int _idx = tid + _i * 256; \
        int _r = _idx >> 3, _c4 = _idx & 7; \
        uint4 _u = make_uint4(f2tf(stA[_i].x), f2tf(stA[_i].y), \
                              f2tf(stA[_i].z), f2tf(stA[_i].w)); \
        *(uint4*)&As[buf][_r * 32 + 4 * (_c4 ^ (_r & 7))] = _u; \
    } \
    _Pragma("unroll") \
    for (int _i = 0; _i < 2; _i++) { \
        int _idx = tid + _i * 256; \
        int _r = _idx >> 3, _c4 = _idx & 7; \
        uint4 _u = make_uint4(f2tf(stB[_i].x), f2tf(stB[_i].y), \
                              f2tf(stB[_i].z), f2tf(stB[_i].w)); \
        *(uint4*)&Bs[buf][_r * 32 + 4 * (_c4 ^ (_r & 7))] = _u; \
    } \
} while (0)

    LDG_CHUNK(0);
    STS_CHUNK(0);
    __syncthreads();

    for (int c = 0; c < NCHUNK; c++) {
        const int buf = c & 1;
        if (c + 1 < NCHUNK) LDG_CHUNK(c + 1);

        const uint32_t* Ab = As[buf];
        const uint32_t* Bb = Bs[buf];
#pragma unroll
        for (int s = 0; s < 4; s++) {
            const int pk0 = (s * 8 + t) ^ (g << 2);
            const int pk1 = pk0 ^ 4;
            uint32_t af[2][4], bf[4][2];
#pragma unroll
            for (int mt = 0; mt < 2; mt++) {
                int r0 = wm * 32 + mt * 16 + g;
                af[mt][0] = Ab[r0 * 32 + pk0];
                af[mt][1] = Ab[(r0 + 8) * 32 + pk0];
                af[mt][2] = Ab[r0 * 32 + pk1];
                af[mt][3] = Ab[(r0 + 8) * 32 + pk1];
            }
#pragma unroll
            for (int nt = 0; nt < 4; nt++) {
                int nr = wn * 32 + nt * 8 + g;
                bf[nt][0] = Bb[nr * 32 + pk0];
                bf[nt][1] = Bb[nr * 32 + pk1];
            }
#pragma unroll
            for (int mt = 0; mt < 2; mt++)
#pragma unroll
                for (int nt = 0; nt < 4; nt++)
                    MMA_TF32(acc[mt][nt], af[mt], bf[nt]);
        }

        if (c + 1 < NCHUNK) STS_CHUNK(buf ^ 1);
        __syncthreads();
    }

    // epilogue: each warp writes its own C fragments (+bias)
    const int h = n0 >> 6;   // BN==HD==64, so one head per block in modes 0-2
    float* qkv = (mode == 0) ? g_q : (mode == 1) ? g_k : g_v;
#pragma unroll
    for (int mt = 0; mt < 2; mt++) {
#pragma unroll
        for (int half = 0; half < 2; half++) {
            int row = m0 + wm * 32 + mt * 16 + g + half * 8;
            int b = row / SS, sx = row % SS;
            float* dst0 = (mode == 3)
                ? (outp + (size_t)row * DD)
                : (qkv + (size_t)((b * HH + h) * SS + sx) * HDIM - n0);
            // dst0 + n gives the right element in both modes (n0..n0+63 range)
#pragma unroll
            for (int nt = 0; nt < 4; nt++) {
                int n = n0 + wn * 32 + nt * 8 + 2 * t;
                float2 bv = *(const float2*)&bias[n];
                float2 r;
                r.x = acc[mt][nt][half * 2 + 0] + bv.x;
                r.y = acc[mt][nt][half * 2 + 1] + bv.y;
                *(float2*)(dst0 + n) = r;
            }
        }
    }
}

// ============================================================================
// Flash attention (unchanged fp32 version; tensor-core port is next round)
// ============================================================================
__global__ void __launch_bounds__(256) attn_kernel()
{
    __shared__ float Qs[QT][QPITCH];
    __shared__ float Ks[KT][QPITCH];
    __shared__ float Vs[KT][QPITCH];
    __shared__ float Ps[QT][PPITCH];

    const int b  = blockIdx.z;
    const int h  = blockIdx.y;
    const int q0 = blockIdx.x * QT;
    const int tid = threadIdx.x;
    const int ty = tid >> 4;
    const int tx = tid & 15;

    const float* qb = g_q + (size_t)((b * HH + h) * SS) * HDIM;
    const float* kb = g_k + (size_t)((b * HH + h) * SS) * HDIM;
    const float* vb = g_v + (size_t)((b * HH + h) * SS) * HDIM;

#pragma unroll
    for (int i = 0; i < 4; i++) {
        int idx = tid + i * 256;
        int r = idx >> 4, c = (idx & 15) << 2;
        int qr = q0 + r;
        float4 v4 = make_float4(0.f, 0.f, 0.f, 0.f);
        if (qr < SS) v4 = *(const float4*)&qb[(size_t)qr * HDIM + c];
        *(float4*)&Qs[r][c] = v4;
    }

    float m_i[4], l_i[4], acc[4][4];
#pragma unroll
    for (int i = 0; i < 4; i++) {
        m_i[i] = -1e30f; l_i[i] = 0.f;
#pragma unroll
        for (int j = 0; j < 4; j++) acc[i][j] = 0.f;
    }
    const float scale = 0.125f;
    const int nkt = (SS + KT - 1) / KT;

    for (int kt = 0; kt < nkt; kt++) {
        int k0 = kt * KT;
#pragma unroll
        for (int i = 0; i < 2; i++) {
            int idx = tid + i * 256;
            int r = idx >> 4, c = (idx & 15) << 2;
            int kr = k0 + r;
            float4 kv4 = make_float4(0.f, 0.f, 0.f, 0.f);
            float4 vv4 = kv4;
            if (kr < SS) {
                kv4 = *(const float4*)&kb[(size_t)kr * HDIM + c];
                vv4 = *(const float4*)&vb[(size_t)kr * HDIM + c];
            }
            *(float4*)&Ks[r][c] = kv4;
            *(float4*)&Vs[r][c] = vv4;
        }
        __syncthreads();

        float s[4][2];
#pragma unroll
        for (int i = 0; i < 4; i++) { s[i][0] = 0.f; s[i][1] = 0.f; }
#pragma unroll
        for (int d4 = 0; d4 < 16; d4++) {
            float4 qv[4], kv[2];
#pragma unroll
            for (int i = 0; i < 4; i++) qv[i] = *(const float4*)&Qs[ty * 4 + i][d4 << 2];
            kv[0] = *(const float4*)&Ks[tx][d4 << 2];
            kv[1] = *(const float4*)&Ks[tx + 16][d4 << 2];
#pragma unroll
            for (int i = 0; i < 4; i++) {
#pragma unroll
                for (int j = 0; j < 2; j++) {
                    s[i][j] = fmaf(qv[i].x, kv[j].x, s[i][j]);
                    s[i][j] = fmaf(qv[i].y, kv[j].y, s[i][j]);
                    s[i][j] = fmaf(qv[i].z, kv[j].z, s[i][j]);
                    s[i][j] = fmaf(qv[i].w, kv[j].w, s[i][j]);
                }
            }
        }
#pragma unroll
        for (int i = 0; i < 4; i++) {
#pragma unroll
            for (int j = 0; j < 2; j++) {
                s[i][j] *= scale;
                if (k0 + tx + 16 * j >= SS) s[i][j] = -1e30f;
            }
        }

#pragma unroll
        for (int i = 0; i < 4; i++) {
            float mx = fmaxf(s[i][0], s[i][1]);
#pragma unroll
            for (int off = 8; off > 0; off >>= 1)
                mx = fmaxf(mx, __shfl_xor_sync(0xffffffffu, mx, off, 16));
            float mnew = fmaxf(m_i[i], mx);
            float alpha = __expf(m_i[i] - mnew);
            float p0 = __expf(s[i][0] - mnew);
            float p1 = __expf(s[i][1] - mnew);
            float ls = p0 + p1;
#pragma unroll
            for (int off = 8; off > 0; off >>= 1)
                ls += __shfl_xor_sync(0xffffffffu, ls, off, 16);
            l_i[i] = l_i[i] * alpha + ls;
            m_i[i] = mnew;
#pragma unroll
            for (int c = 0; c < 4; c++) acc[i][c] *= alpha;
            Ps[ty * 4 + i][tx]      = p0;
            Ps[ty * 4 + i][tx + 16] = p1;
        }
        __syncthreads();

#pragma unroll
        for (int k4 = 0; k4 < KT / 4; k4++) {
            float4 pv[4];
#pragma unroll
            for (int i = 0; i < 4; i++)
                pv[i] = *(const float4*)&Ps[ty * 4 + i][k4 << 2];
#pragma unroll
            for (int kk = 0; kk < 4; kk++) {
                float4 vv = *(const float4*)&Vs[(k4 << 2) + kk][tx << 2];
#pragma unroll
                for (int i = 0; i < 4; i++) {
                    float p = (kk == 0) ? pv[i].x : (kk == 1) ? pv[i].y
                            : (kk == 2) ? pv[i].z : pv[i].w;
                    acc[i][0] = fmaf(p, vv.x, acc[i][0]);
                    acc[i][1] = fmaf(p, vv.y, acc[i][1]);
                    acc[i][2] = fmaf(p, vv.z, acc[i][2]);
                    acc[i][3] = fmaf(p, vv.w, acc[i][3]);
                }
            }
        }
        __syncthreads();
    }

#pragma unroll
    for (int i = 0; i < 4; i++) {
        int qr = q0 + ty * 4 + i;
        if (qr < SS) {
            float inv = 1.0f / l_i[i];
            float4 r;
            r.x = acc[i][0] * inv; r.y = acc[i][1] * inv;
            r.z = acc[i][2] * inv; r.w = acc[i][3] * inv;
            *(float4*)&g_ctx[(size_t)(b * SS + qr) * DD + h * HDIM + (tx << 2)] = r;
        }
    }
}

// ============================================================================
extern "C" void kernel_launch(void* const* d_in, const int* in_sizes, int n_in,
                              void* d_out, int out_size)
{
    const float* x  = (const float*)d_in[0];
    const float* Wq = (const float*)d_in[1];
    const float* bq = (const float*)d_in[2];
    const float* Wk = (const float*)d_in[3];
    const float* bk = (const float*)d_in[4];
    const float* Wv = (const float*)d_in[5];
    const float* bv = (const float*)d_in[6];
    const float* Wp = (const float*)d_in[7];
    const float* bp = (const float*)d_in[8];
    float* out = (float*)d_out;

    dim3 gg(DD / 64, MTOT / 128);   // 16 x 49
    gemm_tf32<<<gg, 256>>>(x, Wq, bq, nullptr, 0);
    gemm_tf32<<<gg, 256>>>(x, Wk, bk, nullptr, 1);
    gemm_tf32<<<gg, 256>>>(x, Wv, bv, nullptr, 2);

    dim3 ga((SS + QT - 1) / QT, HH, BB);  // 25 x 16 x 4
    attn_kernel<<<ga, 256>>>();

    gemm_tf32<<<gg, 256>>>(nullptr, Wp, bp, out, 3);
}

// round 11
// speedup vs baseline: 1.8394x; 1.8394x over previous
#include <cuda_runtime.h>
#include <cstdint>

#define BB   4
#define SS   1568
#define DD   1024
#define HH   16
#define HDIM 64
#define MTOT (BB*SS)          // 6272

// -------- scratch (no allocation allowed; __device__ globals) --------
__device__ float g_q[BB*HH*SS*HDIM];
__device__ float g_k[BB*HH*SS*HDIM];
__device__ float g_v[BB*HH*SS*HDIM];
__device__ float g_ctx[MTOT*DD];

// ============================================================================
// tf32 helpers (sm_80-class PTX — compiles under compute_103)
// ============================================================================
__device__ __forceinline__ uint32_t f2tf(float f) {
    uint32_t u;
    asm("cvt.rna.tf32.f32 %0, %1;" : "=r"(u) : "f"(f));
    return u;
}

#define MMA_TF32(c, a, b) \
    asm volatile("mma.sync.aligned.m16n8k8.row.col.f32.tf32.tf32.f32 " \
        "{%0,%1,%2,%3}, {%4,%5,%6,%7}, {%8,%9}, {%0,%1,%2,%3};" \
        : "+f"((c)[0]), "+f"((c)[1]), "+f"((c)[2]), "+f"((c)[3]) \
        : "r"((a)[0]), "r"((a)[1]), "r"((a)[2]), "r"((a)[3]), \
          "r"((b)[0]), "r"((b)[1]))

// ============================================================================
// tf32 tensor-core GEMM (unchanged from R9): C[m,n] = sum_k A[m,k]*W[n,k]+bias
// ============================================================================
#define NCHUNK 32   // 1024 / 32

__global__ void __launch_bounds__(256, 2) gemm_tf32(
    const float* __restrict__ Ain, const float* __restrict__ W,
    const float* __restrict__ bias, float* __restrict__ outp, int mode)
{
    __shared__ __align__(16) uint32_t As[2][128 * 32];  // 32 KB
    __shared__ __align__(16) uint32_t Bs[2][64 * 32];   // 16 KB

    const float* A = (mode == 3) ? g_ctx : Ain;
    const int tid = threadIdx.x;
    const int wid = tid >> 5;
    const int lid = tid & 31;
    const int wm  = wid >> 1;
    const int wn  = wid & 1;
    const int g   = lid >> 2;
    const int t   = lid & 3;

    const int m0 = blockIdx.y * 128;
    const int n0 = blockIdx.x * 64;

    const float* aP = A + (size_t)m0 * DD;
    const float* wP = W + (size_t)n0 * DD;

    float acc[2][4][4];
#pragma unroll
    for (int mt = 0; mt < 2; mt++)
#pragma unroll
        for (int nt = 0; nt < 4; nt++)
#pragma unroll
            for (int j = 0; j < 4; j++) acc[mt][nt][j] = 0.f;

    float4 stA[4], stB[2];

#define LDG_CHUNK(kc) do { \
    _Pragma("unroll") \
    for (int _i = 0; _i < 4; _i++) { \
        int _idx = tid + _i * 256; \
        int _r = _idx >> 3, _c4 = _idx & 7; \
        stA[_i] = *(const float4*)(aP + (size_t)_r * DD + (kc) * 32 + _c4 * 4); \
    } \
    _Pragma("unroll") \
    for (int _i = 0; _i < 2; _i++) { \
        int _idx = tid + _i * 256; \
        int _r = _idx >> 3, _c4 = _idx & 7; \
        stB[_i] = *(const float4*)(wP + (size_t)_r * DD + (kc) * 32 + _c4 * 4); \
    } \
} while (0)

#define STS_CHUNK(buf) do { \
    _Pragma("unroll") \
    for (int _i = 0; _i < 4; _i++) { \
        int _idx = tid + _i * 256; \
        int _r = _idx >> 3, _c4 = _idx & 7; \
        uint4 _u = make_uint4(f2tf(stA[_i].x), f2tf(stA[_i].y), \
                              f2tf(stA[_i].z), f2tf(stA[_i].w)); \
        *(uint4*)&As[buf][_r * 32 + 4 * (_c4 ^ (_r & 7))] = _u; \
    } \
    _Pragma("unroll") \
    for (int _i = 0; _i < 2; _i++) { \
        int _idx = tid + _i * 256; \
        int _r = _idx >> 3, _c4 = _idx & 7; \
        uint4 _u = make_uint4(f2tf(stB[_i].x), f2tf(stB[_i].y), \
                              f2tf(stB[_i].z), f2tf(stB[_i].w)); \
        *(uint4*)&Bs[buf][_r * 32 + 4 * (_c4 ^ (_r & 7))] = _u; \
    } \
} while (0)

    LDG_CHUNK(0);
    STS_CHUNK(0);
    __syncthreads();

    for (int c = 0; c < NCHUNK; c++) {
        const int buf = c & 1;
        if (c + 1 < NCHUNK) LDG_CHUNK(c + 1);

        const uint32_t* Ab = As[buf];
        const uint32_t* Bb = Bs[buf];
#pragma unroll
        for (int s = 0; s < 4; s++) {
            const int pk0 = (s * 8 + t) ^ (g << 2);
            const int pk1 = pk0 ^ 4;
            uint32_t af[2][4], bf[4][2];
#pragma unroll
            for (int mt = 0; mt < 2; mt++) {
                int r0 = wm * 32 + mt * 16 + g;
                af[mt][0] = Ab[r0 * 32 + pk0];
                af[mt][1] = Ab[(r0 + 8) * 32 + pk0];
                af[mt][2] = Ab[r0 * 32 + pk1];
                af[mt][3] = Ab[(r0 + 8) * 32 + pk1];
            }
#pragma unroll
            for (int nt = 0; nt < 4; nt++) {
                int nr = wn * 32 + nt * 8 + g;
                bf[nt][0] = Bb[nr * 32 + pk0];
                bf[nt][1] = Bb[nr * 32 + pk1];
            }
#pragma unroll
            for (int mt = 0; mt < 2; mt++)
#pragma unroll
                for (int nt = 0; nt < 4; nt++)
                    MMA_TF32(acc[mt][nt], af[mt], bf[nt]);
        }

        if (c + 1 < NCHUNK) STS_CHUNK(buf ^ 1);
        __syncthreads();
    }

    const int h = n0 >> 6;
    float* qkv = (mode == 0) ? g_q : (mode == 1) ? g_k : g_v;
#pragma unroll
    for (int mt = 0; mt < 2; mt++) {
#pragma unroll
        for (int half = 0; half < 2; half++) {
            int row = m0 + wm * 32 + mt * 16 + g + half * 8;
            int b = row / SS, sx = row % SS;
            float* dst0 = (mode == 3)
                ? (outp + (size_t)row * DD)
                : (qkv + (size_t)((b * HH + h) * SS + sx) * HDIM - n0);
#pragma unroll
            for (int nt = 0; nt < 4; nt++) {
                int n = n0 + wn * 32 + nt * 8 + 2 * t;
                float2 bv = *(const float2*)&bias[n];
                float2 r;
                r.x = acc[mt][nt][half * 2 + 0] + bv.x;
                r.y = acc[mt][nt][half * 2 + 1] + bv.y;
                *(float2*)(dst0 + n) = r;
            }
        }
    }
}

// ============================================================================
// Tensor-core flash attention (tf32 mma.sync).
// Grid (13, HH, BB), 256 threads = 8 warps; warp w owns q rows [w*16, w*16+16).
// BQ=128 queries/block, BKV=64 keys/tile, HDIM=64.
// Smem union (34816 B): Q staging phase, then K rows 0-63 | V rows 64-127.
// Fragment indexing (validated in gemm_tf32):
//   A: a0=A[g][k], a1=A[g+8][k], a2=A[g][k+4], a3=A[g+8][k+4], k=8s+t
//   B: b0=B[n=8nt+g][k=8s+t], b1=B[n][k+4]
// S=QK^T: B element (n=key,k=d) -> Ks[key][d] natural layout, conflict-free.
// P*V:    B element (n=d,k=key) -> Vs[key][d] natural layout, <=2-way.
// ============================================================================
#define KVP 68              // smem pitch (words)
#define NKT 25              // ceil(1568/64); 1568 = 24*64 + 32

__global__ void __launch_bounds__(256) attn_mma()
{
    __shared__ __align__(16) uint32_t smu[128 * KVP];   // 34816 B

    const int b  = blockIdx.z;
    const int h  = blockIdx.y;
    const int q0 = blockIdx.x * 128;
    const int tid = threadIdx.x;
    const int w   = tid >> 5;
    const int lid = tid & 31;
    const int g   = lid >> 2;
    const int t   = lid & 3;

    const float* qb = g_q + (size_t)(b * HH + h) * SS * HDIM;
    const float* kb = g_k + (size_t)(b * HH + h) * SS * HDIM;
    const float* vb = g_v + (size_t)(b * HH + h) * SS * HDIM;

    // ---- stage Q (128x64) into smem, pre-scaled by 1/8 (exact), tf32 ----
#pragma unroll
    for (int i = 0; i < 8; i++) {
        int idx = tid + i * 256;
        int r = idx >> 4, c4 = idx & 15;
        int qr = q0 + r; if (qr >= SS) qr = SS - 1;
        float4 v = *(const float4*)(qb + (size_t)qr * HDIM + c4 * 4);
        uint4 u = make_uint4(f2tf(v.x * 0.125f), f2tf(v.y * 0.125f),
                             f2tf(v.z * 0.125f), f2tf(v.w * 0.125f));
        *(uint4*)&smu[r * KVP + c4 * 4] = u;
    }
    __syncthreads();

    // ---- Q fragments to registers (held for whole kernel) ----
    uint32_t qf[8][4];
    {
        const int r0 = (w * 16 + g) * KVP;
        const int r8 = r0 + 8 * KVP;
#pragma unroll
        for (int s = 0; s < 8; s++) {
            qf[s][0] = smu[r0 + 8 * s + t];
            qf[s][1] = smu[r8 + 8 * s + t];
            qf[s][2] = smu[r0 + 8 * s + t + 4];
            qf[s][3] = smu[r8 + 8 * s + t + 4];
        }
    }
    __syncthreads();   // Q region about to be overwritten by K/V

    // ---- K/V register prefetch ----
    float4 kf[4], vf[4];
#define LDGKV(kt_) do { \
    _Pragma("unroll") \
    for (int _i = 0; _i < 4; _i++) { \
        int _idx = tid + _i * 256; \
        int _r = _idx >> 4, _c4 = _idx & 15; \
        int _kr = (kt_) * 64 + _r; if (_kr >= SS) _kr = SS - 1; \
        kf[_i] = *(const float4*)(kb + (size_t)_kr * HDIM + _c4 * 4); \
        vf[_i] = *(const float4*)(vb + (size_t)_kr * HDIM + _c4 * 4); \
    } \
} while (0)

    LDGKV(0);

    float m0v = -1e30f, m1v = -1e30f, l0 = 0.f, l1 = 0.f;
    float ao[8][4];
#pragma unroll
    for (int nt = 0; nt < 8; nt++)
#pragma unroll
        for (int j = 0; j < 4; j++) ao[nt][j] = 0.f;

    const int srcA = (lid & ~3) | (t >> 1);
    const int srcB = srcA + 2;
    const bool sel = (t & 1) != 0;

    for (int kt = 0; kt < NKT; kt++) {
        // store current K/V tile (tf32) — K at rows 0..63, V at word 64*KVP
#pragma unroll
        for (int i = 0; i < 4; i++) {
            int idx = tid + i * 256;
            int r = idx >> 4, c4 = idx & 15;
            *(uint4*)&smu[r * KVP + c4 * 4] =
                make_uint4(f2tf(kf[i].x), f2tf(kf[i].y), f2tf(kf[i].z), f2tf(kf[i].w));
            *(uint4*)&smu[64 * KVP + r * KVP + c4 * 4] =
                make_uint4(f2tf(vf[i].x), f2tf(vf[i].y), f2tf(vf[i].z), f2tf(vf[i].w));
        }
        __syncthreads();
        if (kt + 1 < NKT) LDGKV(kt + 1);

        // ---- S = Q K^T  (scores already scaled via Q) ----
        float sf[8][4];
#pragma unroll
        for (int nt = 0; nt < 8; nt++)
#pragma unroll
            for (int j = 0; j < 4; j++) sf[nt][j] = 0.f;
#pragma unroll
        for (int s = 0; s < 8; s++) {
#pragma unroll
            for (int nt = 0; nt < 8; nt++) {
                uint32_t bf[2];
                int ra = (8 * nt + g) * KVP + 8 * s + t;
                bf[0] = smu[ra];
                bf[1] = smu[ra + 4];
                MMA_TF32(sf[nt], qf[s], bf);
            }
        }
        // tail mask: 1568 = 24*64 + 32 -> last tile, n-tiles 4..7 invalid
        if (kt == NKT - 1) {
#pragma unroll
            for (int nt = 4; nt < 8; nt++) {
                sf[nt][0] = -1e30f; sf[nt][1] = -1e30f;
                sf[nt][2] = -1e30f; sf[nt][3] = -1e30f;
            }
        }

        // ---- online softmax (rows g and g+8; quad reduce over t) ----
        float mx0 = -1e30f, mx1 = -1e30f;
#pragma unroll
        for (int nt = 0; nt < 8; nt++) {
            mx0 = fmaxf(mx0, fmaxf(sf[nt][0], sf[nt][1]));
            mx1 = fmaxf(mx1, fmaxf(sf[nt][2], sf[nt][3]));
        }
        mx0 = fmaxf(mx0, __shfl_xor_sync(0xffffffffu, mx0, 1));
        mx0 = fmaxf(mx0, __shfl_xor_sync(0xffffffffu, mx0, 2));
        mx1 = fmaxf(mx1, __shfl_xor_sync(0xffffffffu, mx1, 1));
        mx1 = fmaxf(mx1, __shfl_xor_sync(0xffffffffu, mx1, 2));
        const float mn0 = fmaxf(m0v, mx0);
        const float mn1 = fmaxf(m1v, mx1);
        const float a0 = __expf(m0v - mn0);
        const float a1 = __expf(m1v - mn1);
        m0v = mn0; m1v = mn1;

        uint32_t pf[8][4];
        float s0 = 0.f, s1 = 0.f;
#pragma unroll
        for (int nt = 0; nt < 8; nt++) {
            float e0 = __expf(sf[nt][0] - mn0);
            float e1 = __expf(sf[nt][1] - mn0);
            float e2 = __expf(sf[nt][2] - mn1);
            float e3 = __expf(sf[nt][3] - mn1);
            s0 += e0 + e1; s1 += e2 + e3;
            pf[nt][0] = f2tf(e0); pf[nt][1] = f2tf(e1);
            pf[nt][2] = f2tf(e2); pf[nt][3] = f2tf(e3);
        }
        s0 += __shfl_xor_sync(0xffffffffu, s0, 1);
        s0 += __shfl_xor_sync(0xffffffffu, s0, 2);
        s1 += __shfl_xor_sync(0xffffffffu, s1, 1);
        s1 += __shfl_xor_sync(0xffffffffu, s1, 2);
        l0 = l0 * a0 + s0;
        l1 = l1 * a1 + s1;
#pragma unroll
        for (int nt = 0; nt < 8; nt++) {
            ao[nt][0] *= a0; ao[nt][1] *= a0;
            ao[nt][2] *= a1; ao[nt][3] *= a1;
        }

        // ---- O += P V : A-frags from P via quad shfl, B from Vs natural ----
        const uint32_t* Vb = smu + 64 * KVP;
#pragma unroll
        for (int s = 0; s < 8; s++) {
            uint32_t x0 = __shfl_sync(0xffffffffu, pf[s][0], srcA);
            uint32_t x1 = __shfl_sync(0xffffffffu, pf[s][1], srcA);
            uint32_t y0 = __shfl_sync(0xffffffffu, pf[s][2], srcA);
            uint32_t y1 = __shfl_sync(0xffffffffu, pf[s][3], srcA);
            uint32_t X0 = __shfl_sync(0xffffffffu, pf[s][0], srcB);
            uint32_t X1 = __shfl_sync(0xffffffffu, pf[s][1], srcB);
            uint32_t Y0 = __shfl_sync(0xffffffffu, pf[s][2], srcB);
            uint32_t Y1 = __shfl_sync(0xffffffffu, pf[s][3], srcB);
            uint32_t af[4];
            af[0] = sel ? x1 : x0;   // P[g   ][8s+t]
            af[1] = sel ? y1 : y0;   // P[g+8 ][8s+t]
            af[2] = sel ? X1 : X0;   // P[g   ][8s+t+4]
            af[3] = sel ? Y1 : Y0;   // P[g+8 ][8s+t+4]
#pragma unroll
            for (int nt = 0; nt < 8; nt++) {
                uint32_t bf[2];
                int rb = (8 * s + t) * KVP + 8 * nt + g;
                bf[0] = Vb[rb];
                bf[1] = Vb[rb + 4 * KVP];
                MMA_TF32(ao[nt], af, bf);
            }
        }
        __syncthreads();
    }

    // ---- epilogue: normalize, write ctx [B,S,D] ----
    const float i0 = 1.f / l0;
    const float i1 = 1.f / l1;
    const int qg = q0 + w * 16 + g;
    if (qg < SS) {
        float* row = g_ctx + (size_t)(b * SS + qg) * DD + h * HDIM;
#pragma unroll
        for (int nt = 0; nt < 8; nt++) {
            float2 r; r.x = ao[nt][0] * i0; r.y = ao[nt][1] * i0;
            *(float2*)&row[nt * 8 + 2 * t] = r;
        }
    }
    if (qg + 8 < SS) {
        float* row = g_ctx + (size_t)(b * SS + qg + 8) * DD + h * HDIM;
#pragma unroll
        for (int nt = 0; nt < 8; nt++) {
            float2 r; r.x = ao[nt][2] * i1; r.y = ao[nt][3] * i1;
            *(float2*)&row[nt * 8 + 2 * t] = r;
        }
    }
}

// ============================================================================
extern "C" void kernel_launch(void* const* d_in, const int* in_sizes, int n_in,
                              void* d_out, int out_size)
{
    const float* x  = (const float*)d_in[0];
    const float* Wq = (const float*)d_in[1];
    const float* bq = (const float*)d_in[2];
    const float* Wk = (const float*)d_in[3];
    const float* bk = (const float*)d_in[4];
    const float* Wv = (const float*)d_in[5];
    const float* bv = (const float*)d_in[6];
    const float* Wp = (const float*)d_in[7];
    const float* bp = (const float*)d_in[8];
    float* out = (float*)d_out;

    dim3 gg(DD / 64, MTOT / 128);   // 16 x 49
    gemm_tf32<<<gg, 256>>>(x, Wq, bq, nullptr, 0);
    gemm_tf32<<<gg, 256>>>(x, Wk, bk, nullptr, 1);
    gemm_tf32<<<gg, 256>>>(x, Wv, bv, nullptr, 2);

    dim3 ga((SS + 127) / 128, HH, BB);  // 13 x 16 x 4
    attn_mma<<<ga, 256>>>();

    gemm_tf32<<<gg, 256>>>(nullptr, Wp, bp, out, 3);
}

// round 12
// speedup vs baseline: 1.9080x; 1.0373x over previous
#include <cuda_runtime.h>
#include <cstdint>

#define BB   4
#define SS   1568
#define DD   1024
#define HH   16
#define HDIM 64
#define MTOT (BB*SS)          // 6272

// -------- scratch (no allocation allowed; __device__ globals) --------
__device__ float g_q[BB*HH*SS*HDIM];   // holds tf32-rounded, 0.125-scaled Q
__device__ float g_k[BB*HH*SS*HDIM];   // tf32-rounded K
__device__ float g_v[BB*HH*SS*HDIM];   // tf32-rounded V
__device__ float g_ctx[MTOT*DD];

// ============================================================================
// tf32 / async helpers (sm_80-class PTX — compiles under compute_103)
// ============================================================================
__device__ __forceinline__ uint32_t f2tf(float f) {
    uint32_t u;
    asm("cvt.rna.tf32.f32 %0, %1;" : "=r"(u) : "f"(f));
    return u;
}
__device__ __forceinline__ uint32_t smem_u32(const void* p) {
    uint32_t a;
    asm("{ .reg .u64 t; cvta.to.shared.u64 t, %1; cvt.u32.u64 %0, t; }"
        : "=r"(a) : "l"(p));
    return a;
}
__device__ __forceinline__ void cp_async16(uint32_t dst, const void* src) {
    asm volatile("cp.async.cg.shared.global [%0], [%1], 16;"
                 :: "r"(dst), "l"(src) : "memory");
}
#define CP_COMMIT() asm volatile("cp.async.commit_group;" ::: "memory")
#define CP_WAIT(n)  asm volatile("cp.async.wait_group %0;" :: "n"(n) : "memory")

#define MMA_TF32(c, a, b) \
    asm volatile("mma.sync.aligned.m16n8k8.row.col.f32.tf32.tf32.f32 " \
        "{%0,%1,%2,%3}, {%4,%5,%6,%7}, {%8,%9}, {%0,%1,%2,%3};" \
        : "+f"((c)[0]), "+f"((c)[1]), "+f"((c)[2]), "+f"((c)[3]) \
        : "r"((a)[0]), "r"((a)[1]), "r"((a)[2]), "r"((a)[3]), \
          "r"((b)[0]), "r"((b)[1]))

// ============================================================================
// tf32 tensor-core GEMM (mainloop unchanged from R9).
// Epilogue: modes 0-2 store tf32-rounded values (Q also pre-scaled by 1/8)
// so the attention kernel consumes MMA-ready bits with zero conversions.
// ============================================================================
#define NCHUNK 32   // 1024 / 32

__global__ void __launch_bounds__(256, 2) gemm_tf32(
    const float* __restrict__ Ain, const float* __restrict__ W,
    const float* __restrict__ bias, float* __restrict__ outp, int mode)
{
    __shared__ __align__(16) uint32_t As[2][128 * 32];  // 32 KB
    __shared__ __align__(16) uint32_t Bs[2][64 * 32];   // 16 KB

    const float* A = (mode == 3) ? g_ctx : Ain;
    const int tid = threadIdx.x;
    const int wid = tid >> 5;
    const int lid = tid & 31;
    const int wm  = wid >> 1;
    const int wn  = wid & 1;
    const int g   = lid >> 2;
    const int t   = lid & 3;

    const int m0 = blockIdx.y * 128;
    const int n0 = blockIdx.x * 64;

    const float* aP = A + (size_t)m0 * DD;
    const float* wP = W + (size_t)n0 * DD;

    float acc[2][4][4];
#pragma unroll
    for (int mt = 0; mt < 2; mt++)
#pragma unroll
        for (int nt = 0; nt < 4; nt++)
#pragma unroll
            for (int j = 0; j < 4; j++) acc[mt][nt][j] = 0.f;

    float4 stA[4], stB[2];

#define LDG_CHUNK(kc) do { \
    _Pragma("unroll") \
    for (int _i = 0; _i < 4; _i++) { \
        int _idx = tid + _i * 256; \
        int _r = _idx >> 3, _c4 = _idx & 7; \
        stA[_i] = *(const float4*)(aP + (size_t)_r * DD + (kc) * 32 + _c4 * 4); \
    } \
    _Pragma("unroll") \
    for (int _i = 0; _i < 2; _i++) { \
        int _idx = tid + _i * 256; \
        int _r = _idx >> 3, _c4 = _idx & 7; \
        stB[_i] = *(const float4*)(wP + (size_t)_r * DD + (kc) * 32 + _c4 * 4); \
    } \
} while (0)

#define STS_CHUNK(buf) do { \
    _Pragma("unroll") \
    for (int _i = 0; _i < 4; _i++) { \
        int _idx = tid + _i * 256; \
        int _r = _idx >> 3, _c4 = _idx & 7; \
        uint4 _u = make_uint4(f2tf(stA[_i].x), f2tf(stA[_i].y), \
                              f2tf(stA[_i].z), f2tf(stA[_i].w)); \
        *(uint4*)&As[buf][_r * 32 + 4 * (_c4 ^ (_r & 7))] = _u; \
    } \
    _Pragma("unroll") \
    for (int _i = 0; _i < 2; _i++) { \
        int _idx = tid + _i * 256; \
        int _r = _idx >> 3, _c4 = _idx & 7; \
        uint4 _u = make_uint4(f2tf(stB[_i].x), f2tf(stB[_i].y), \
                              f2tf(stB[_i].z), f2tf(stB[_i].w)); \
        *(uint4*)&Bs[buf][_r * 32 + 4 * (_c4 ^ (_r & 7))] = _u; \
    } \
} while (0)

    LDG_CHUNK(0);
    STS_CHUNK(0);
    __syncthreads();

    for (int c = 0; c < NCHUNK; c++) {
        const int buf = c & 1;
        if (c + 1 < NCHUNK) LDG_CHUNK(c + 1);

        const uint32_t* Ab = As[buf];
        const uint32_t* Bb = Bs[buf];
#pragma unroll
        for (int s = 0; s < 4; s++) {
            const int pk0 = (s * 8 + t) ^ (g << 2);
            const int pk1 = pk0 ^ 4;
            uint32_t af[2][4], bf[4][2];
#pragma unroll
            for (int mt = 0; mt < 2; mt++) {
                int r0 = wm * 32 + mt * 16 + g;
                af[mt][0] = Ab[r0 * 32 + pk0];
                af[mt][1] = Ab[(r0 + 8) * 32 + pk0];
                af[mt][2] = Ab[r0 * 32 + pk1];
                af[mt][3] = Ab[(r0 + 8) * 32 + pk1];
            }
#pragma unroll
            for (int nt = 0; nt < 4; nt++) {
                int nr = wn * 32 + nt * 8 + g;
                bf[nt][0] = Bb[nr * 32 + pk0];
                bf[nt][1] = Bb[nr * 32 + pk1];
            }
#pragma unroll
            for (int mt = 0; mt < 2; mt++)
#pragma unroll
                for (int nt = 0; nt < 4; nt++)
                    MMA_TF32(acc[mt][nt], af[mt], bf[nt]);
        }

        if (c + 1 < NCHUNK) STS_CHUNK(buf ^ 1);
        __syncthreads();
    }

    const int h = n0 >> 6;
    float* qkv = (mode == 0) ? g_q : (mode == 1) ? g_k : g_v;
    const float sc = (mode == 0) ? 0.125f : 1.0f;
#pragma unroll
    for (int mt = 0; mt < 2; mt++) {
#pragma unroll
        for (int half = 0; half < 2; half++) {
            int row = m0 + wm * 32 + mt * 16 + g + half * 8;
            int b = row / SS, sx = row % SS;
            float* dst0 = (mode == 3)
                ? (outp + (size_t)row * DD)
                : (qkv + (size_t)((b * HH + h) * SS + sx) * HDIM - n0);
#pragma unroll
            for (int nt = 0; nt < 4; nt++) {
                int n = n0 + wn * 32 + nt * 8 + 2 * t;
                float2 bv = *(const float2*)&bias[n];
                float2 r;
                r.x = acc[mt][nt][half * 2 + 0] + bv.x;
                r.y = acc[mt][nt][half * 2 + 1] + bv.y;
                if (mode != 3) {
                    r.x = __uint_as_float(f2tf(r.x * sc));
                    r.y = __uint_as_float(f2tf(r.y * sc));
                }
                *(float2*)(dst0 + n) = r;
            }
        }
    }
}

// ============================================================================
// Tensor-core flash attention, cp.async double-buffered.
// Q/K/V in gmem are already tf32 bits (Q pre-scaled by 1/8) — zero cvts here.
// Smem (dynamic, 69632 B): buf{0,1}, each K(64x68) @ +0 | V(64x68) @ +4352 w.
// Q stages via cp.async into buf1 before the loop.
// ============================================================================
#define KVP 68              // smem pitch (words)
#define BUFW 8704           // words per buffer (2 * 64 * 68)
#define NKT 25              // ceil(1568/64); 1568 = 24*64 + 32
#define ATTN_SMEM (2 * BUFW * 4)   // 69632 B

__global__ void __launch_bounds__(256, 2) attn_mma()
{
    extern __shared__ __align__(16) uint32_t smw[];
    const uint32_t sbase = smem_u32(smw);

    const int b  = blockIdx.z;
    const int h  = blockIdx.y;
    const int q0 = blockIdx.x * 128;
    const int tid = threadIdx.x;
    const int w   = tid >> 5;
    const int lid = tid & 31;
    const int g   = lid >> 2;
    const int t   = lid & 3;

    const float* qb = g_q + (size_t)(b * HH + h) * SS * HDIM;
    const float* kb = g_k + (size_t)(b * HH + h) * SS * HDIM;
    const float* vb = g_v + (size_t)(b * HH + h) * SS * HDIM;

    // per-thread cp.async coordinates: 4 chunks cover a 64x64 tile in 16B units
    const int cr  = tid >> 4;          // row 0..15 (+16 per chunk... see loops)
    const int cc4 = tid & 15;          // 16B column 0..15

#define CPA_KV(kt_, buf_) do { \
    _Pragma("unroll") \
    for (int _i = 0; _i < 4; _i++) { \
        int _r = cr + _i * 16; \
        int _kr = (kt_) * 64 + _r; if (_kr >= SS) _kr = SS - 1; \
        uint32_t _d = sbase + ((buf_) * BUFW + _r * KVP + cc4 * 4) * 4; \
        cp_async16(_d,            kb + (size_t)_kr * HDIM + cc4 * 4); \
        cp_async16(_d + 4352 * 4, vb + (size_t)_kr * HDIM + cc4 * 4); \
    } \
} while (0)

    // ---- stage Q (128x64) into buf1 via cp.async; KV0 into buf0 ----
#pragma unroll
    for (int i = 0; i < 8; i++) {
        int r = cr + i * 16;
        int qr = q0 + r; if (qr >= SS) qr = SS - 1;
        uint32_t d = sbase + (BUFW + r * KVP + cc4 * 4) * 4;
        cp_async16(d, qb + (size_t)qr * HDIM + cc4 * 4);
    }
    CP_COMMIT();                      // group: Q
    CPA_KV(0, 0);
    CP_COMMIT();                      // group: KV0
    CP_WAIT(1);                       // Q done
    __syncthreads();

    // ---- Q fragments to registers ----
    uint32_t qf[8][4];
    {
        const uint32_t* Qb = smw + BUFW;
        const int r0 = (w * 16 + g) * KVP;
        const int r8 = r0 + 8 * KVP;
#pragma unroll
        for (int s = 0; s < 8; s++) {
            qf[s][0] = Qb[r0 + 8 * s + t];
            qf[s][1] = Qb[r8 + 8 * s + t];
            qf[s][2] = Qb[r0 + 8 * s + t + 4];
            qf[s][3] = Qb[r8 + 8 * s + t + 4];
        }
    }
    __syncthreads();                  // all qf reads done before buf1 reuse
    CPA_KV(1, 1);
    CP_COMMIT();                      // group: KV1

    float m0v = -1e30f, m1v = -1e30f, l0 = 0.f, l1 = 0.f;
    float ao[8][4];
#pragma unroll
    for (int nt = 0; nt < 8; nt++)
#pragma unroll
        for (int j = 0; j < 4; j++) ao[nt][j] = 0.f;

    const int srcA = (lid & ~3) | (t >> 1);
    const int srcB = srcA + 2;
    const bool sel = (t & 1) != 0;

    for (int kt = 0; kt < NKT; kt++) {
        if (kt == NKT - 1) CP_WAIT(0); else CP_WAIT(1);
        __syncthreads();

        const uint32_t* Kb = smw + (kt & 1) * BUFW;
        const uint32_t* Vb = Kb + 4352;

        // ---- S = Q K^T ----
        float sf[8][4];
#pragma unroll
        for (int nt = 0; nt < 8; nt++)
#pragma unroll
            for (int j = 0; j < 4; j++) sf[nt][j] = 0.f;
#pragma unroll
        for (int s = 0; s < 8; s++) {
#pragma unroll
            for (int nt = 0; nt < 8; nt++) {
                uint32_t bf[2];
                int ra = (8 * nt + g) * KVP + 8 * s + t;
                bf[0] = Kb[ra];
                bf[1] = Kb[ra + 4];
                MMA_TF32(sf[nt], qf[s], bf);
            }
        }
        if (kt == NKT - 1) {          // 1568 = 24*64+32: n-tiles 4..7 invalid
#pragma unroll
            for (int nt = 4; nt < 8; nt++) {
                sf[nt][0] = -1e30f; sf[nt][1] = -1e30f;
                sf[nt][2] = -1e30f; sf[nt][3] = -1e30f;
            }
        }

        // ---- online softmax (rows g, g+8; quad reduce over t) ----
        float mx0 = -1e30f, mx1 = -1e30f;
#pragma unroll
        for (int nt = 0; nt < 8; nt++) {
            mx0 = fmaxf(mx0, fmaxf(sf[nt][0], sf[nt][1]));
            mx1 = fmaxf(mx1, fmaxf(sf[nt][2], sf[nt][3]));
        }
        mx0 = fmaxf(mx0, __shfl_xor_sync(0xffffffffu, mx0, 1));
        mx0 = fmaxf(mx0, __shfl_xor_sync(0xffffffffu, mx0, 2));
        mx1 = fmaxf(mx1, __shfl_xor_sync(0xffffffffu, mx1, 1));
        mx1 = fmaxf(mx1, __shfl_xor_sync(0xffffffffu, mx1, 2));
        const float mn0 = fmaxf(m0v, mx0);
        const float mn1 = fmaxf(m1v, mx1);
        const float a0 = __expf(m0v - mn0);
        const float a1 = __expf(m1v - mn1);
        m0v = mn0; m1v = mn1;

        float s0 = 0.f, s1 = 0.f;
#pragma unroll
        for (int nt = 0; nt < 8; nt++) {       // P overwrites sf in place
            float e0 = __expf(sf[nt][0] - mn0);
            float e1 = __expf(sf[nt][1] - mn0);
            float e2 = __expf(sf[nt][2] - mn1);
            float e3 = __expf(sf[nt][3] - mn1);
            s0 += e0 + e1; s1 += e2 + e3;
            sf[nt][0] = __uint_as_float(f2tf(e0));
            sf[nt][1] = __uint_as_float(f2tf(e1));
            sf[nt][2] = __uint_as_float(f2tf(e2));
            sf[nt][3] = __uint_as_float(f2tf(e3));
        }
        s0 += __shfl_xor_sync(0xffffffffu, s0, 1);
        s0 += __shfl_xor_sync(0xffffffffu, s0, 2);
        s1 += __shfl_xor_sync(0xffffffffu, s1, 1);
        s1 += __shfl_xor_sync(0xffffffffu, s1, 2);
        l0 = l0 * a0 + s0;
        l1 = l1 * a1 + s1;
#pragma unroll
        for (int nt = 0; nt < 8; nt++) {
            ao[nt][0] *= a0; ao[nt][1] *= a0;
            ao[nt][2] *= a1; ao[nt][3] *= a1;
        }

        // ---- O += P V : A-frags via quad shfl of P bits, B from Vs ----
#pragma unroll
        for (int s = 0; s < 8; s++) {
            float x0 = __shfl_sync(0xffffffffu, sf[s][0], srcA);
            float x1 = __shfl_sync(0xffffffffu, sf[s][1], srcA);
            float y0 = __shfl_sync(0xffffffffu, sf[s][2], srcA);
            float y1 = __shfl_sync(0xffffffffu, sf[s][3], srcA);
            float X0 = __shfl_sync(0xffffffffu, sf[s][0], srcB);
            float X1 = __shfl_sync(0xffffffffu, sf[s][1], srcB);
            float Y0 = __shfl_sync(0xffffffffu, sf[s][2], srcB);
            float Y1 = __shfl_sync(0xffffffffu, sf[s][3], srcB);
            uint32_t af[4];
            af[0] = __float_as_uint(sel ? x1 : x0);   // P[g   ][8s+t]
            af[1] = __float_as_uint(sel ? y1 : y0);   // P[g+8 ][8s+t]
            af[2] = __float_as_uint(sel ? X1 : X0);   // P[g   ][8s+t+4]
            af[3] = __float_as_uint(sel ? Y1 : Y0);   // P[g+8 ][8s+t+4]
#pragma unroll
            for (int nt = 0; nt < 8; nt++) {
                uint32_t bf[2];
                int rb = (8 * s + t) * KVP + 8 * nt + g;
                bf[0] = Vb[rb];
                bf[1] = Vb[rb + 4 * KVP];
                MMA_TF32(ao[nt], af, bf);
            }
        }
        __syncthreads();
        if (kt + 2 < NKT) { CPA_KV(kt + 2, kt & 1); CP_COMMIT(); }
    }

    // ---- epilogue: normalize, write ctx [B,S,D] ----
    const float i0 = 1.f / l0;
    const float i1 = 1.f / l1;
    const int qg = q0 + w * 16 + g;
    if (qg < SS) {
        float* row = g_ctx + (size_t)(b * SS + qg) * DD + h * HDIM;
#pragma unroll
        for (int nt = 0; nt < 8; nt++) {
            float2 r; r.x = ao[nt][0] * i0; r.y = ao[nt][1] * i0;
            *(float2*)&row[nt * 8 + 2 * t] = r;
        }
    }
    if (qg + 8 < SS) {
        float* row = g_ctx + (size_t)(b * SS + qg + 8) * DD + h * HDIM;
#pragma unroll
        for (int nt = 0; nt < 8; nt++) {
            float2 r; r.x = ao[nt][2] * i1; r.y = ao[nt][3] * i1;
            *(float2*)&row[nt * 8 + 2 * t] = r;
        }
    }
}

// ============================================================================
extern "C" void kernel_launch(void* const* d_in, const int* in_sizes, int n_in,
                              void* d_out, int out_size)
{
    const float* x  = (const float*)d_in[0];
    const float* Wq = (const float*)d_in[1];
    const float* bq = (const float*)d_in[2];
    const float* Wk = (const float*)d_in[3];
    const float* bk = (const float*)d_in[4];
    const float* Wv = (const float*)d_in[5];
    const float* bv = (const float*)d_in[6];
    const float* Wp = (const float*)d_in[7];
    const float* bp = (const float*)d_in[8];
    float* out = (float*)d_out;

    cudaFuncSetAttribute(attn_mma, cudaFuncAttributeMaxDynamicSharedMemorySize,
                         ATTN_SMEM);

    dim3 gg(DD / 64, MTOT / 128);   // 16 x 49
    gemm_tf32<<<gg, 256>>>(x, Wq, bq, nullptr, 0);
    gemm_tf32<<<gg, 256>>>(x, Wk, bk, nullptr, 1);
    gemm_tf32<<<gg, 256>>>(x, Wv, bv, nullptr, 2);

    dim3 ga((SS + 127) / 128, HH, BB);  // 13 x 16 x 4
    attn_mma<<<ga, 256, ATTN_SMEM>>>();

    gemm_tf32<<<gg, 256>>>(nullptr, Wp, bp, out, 3);
}

// round 13
// speedup vs baseline: 1.9120x; 1.0021x over previous
#include <cuda_runtime.h>
#include <cstdint>

#define BB   4
#define SS   1568
#define DD   1024
#define HH   16
#define HDIM 64
#define MTOT (BB*SS)          // 6272

// -------- scratch (no allocation allowed; __device__ globals) --------
__device__ float g_q[BB*HH*SS*HDIM];   // tf32-rounded, 0.125-scaled Q
__device__ float g_k[BB*HH*SS*HDIM];   // tf32-rounded K
__device__ float g_v[BB*HH*SS*HDIM];   // tf32-rounded V
__device__ float g_ctx[MTOT*DD];

// ============================================================================
// tf32 / async helpers (sm_80-class PTX — compiles under compute_103)
// ============================================================================
__device__ __forceinline__ uint32_t f2tf(float f) {
    uint32_t u;
    asm("cvt.rna.tf32.f32 %0, %1;" : "=r"(u) : "f"(f));
    return u;
}
__device__ __forceinline__ uint32_t smem_u32(const void* p) {
    uint32_t a;
    asm("{ .reg .u64 t; cvta.to.shared.u64 t, %1; cvt.u32.u64 %0, t; }"
        : "=r"(a) : "l"(p));
    return a;
}
__device__ __forceinline__ void cp_async16(uint32_t dst, const void* src) {
    asm volatile("cp.async.cg.shared.global [%0], [%1], 16;"
                 :: "r"(dst), "l"(src) : "memory");
}
#define CP_COMMIT() asm volatile("cp.async.commit_group;" ::: "memory")
#define CP_WAIT(n)  asm volatile("cp.async.wait_group %0;" :: "n"(n) : "memory")

#define MMA_TF32(c, a, b) \
    asm volatile("mma.sync.aligned.m16n8k8.row.col.f32.tf32.tf32.f32 " \
        "{%0,%1,%2,%3}, {%4,%5,%6,%7}, {%8,%9}, {%0,%1,%2,%3};" \
        : "+f"((c)[0]), "+f"((c)[1]), "+f"((c)[2]), "+f"((c)[3]) \
        : "r"((a)[0]), "r"((a)[1]), "r"((a)[2]), "r"((a)[3]), \
          "r"((b)[0]), "r"((b)[1]))

// 4x (8 rows x 16B) tile load; lane l supplies row l&7 of matrix l>>3.
// As 32-bit elements: lane 4r+c of each matrix receives (row r, col c).
#define LDMX4(r0, r1, r2, r3, addr) \
    asm volatile("ldmatrix.sync.aligned.m8n8.x4.shared.b16 {%0,%1,%2,%3}, [%4];" \
        : "=r"(r0), "=r"(r1), "=r"(r2), "=r"(r3) : "r"(addr))

// ============================================================================
// tf32 tensor-core GEMM (unchanged — passing at rel_err 5.4e-4).
// Epilogue stores tf32-rounded Q(*0.125)/K/V so attention does zero cvts.
// ============================================================================
#define NCHUNK 32   // 1024 / 32

__global__ void __launch_bounds__(256, 2) gemm_tf32(
    const float* __restrict__ Ain, const float* __restrict__ W,
    const float* __restrict__ bias, float* __restrict__ outp, int mode)
{
    __shared__ __align__(16) uint32_t As[2][128 * 32];  // 32 KB
    __shared__ __align__(16) uint32_t Bs[2][64 * 32];   // 16 KB

    const float* A = (mode == 3) ? g_ctx : Ain;
    const int tid = threadIdx.x;
    const int wid = tid >> 5;
    const int lid = tid & 31;
    const int wm  = wid >> 1;
    const int wn  = wid & 1;
    const int g   = lid >> 2;
    const int t   = lid & 3;

    const int m0 = blockIdx.y * 128;
    const int n0 = blockIdx.x * 64;

    const float* aP = A + (size_t)m0 * DD;
    const float* wP = W + (size_t)n0 * DD;

    float acc[2][4][4];
#pragma unroll
    for (int mt = 0; mt < 2; mt++)
#pragma unroll
        for (int nt = 0; nt < 4; nt++)
#pragma unroll
            for (int j = 0; j < 4; j++) acc[mt][nt][j] = 0.f;

    float4 stA[4], stB[2];

#define LDG_CHUNK(kc) do { \
    _Pragma("unroll") \
    for (int _i = 0; _i < 4; _i++) { \
        int _idx = tid + _i * 256; \
        int _r = _idx >> 3, _c4 = _idx & 7; \
        stA[_i] = *(const float4*)(aP + (size_t)_r * DD + (kc) * 32 + _c4 * 4); \
    } \
    _Pragma("unroll") \
    for (int _i = 0; _i < 2; _i++) { \
        int _idx = tid + _i * 256; \
        int _r = _idx >> 3, _c4 = _idx & 7; \
        stB[_i] = *(const float4*)(wP + (size_t)_r * DD + (kc) * 32 + _c4 * 4); \
    } \
} while (0)

#define STS_CHUNK(buf) do { \
    _Pragma("unroll") \
    for (int _i = 0; _i < 4; _i++) { \
        int _idx = tid + _i * 256; \
        int _r = _idx >> 3, _c4 = _idx & 7; \
        uint4 _u = make_uint4(f2tf(stA[_i].x), f2tf(stA[_i].y), \
                              f2tf(stA[_i].z), f2tf(stA[_i].w)); \
        *(uint4*)&As[buf][_r * 32 + 4 * (_c4 ^ (_r & 7))] = _u; \
    } \
    _Pragma("unroll") \
    for (int _i = 0; _i < 2; _i++) { \
        int _idx = tid + _i * 256; \
        int _r = _idx >> 3, _c4 = _idx & 7; \
        uint4 _u = make_uint4(f2tf(stB[_i].x), f2tf(stB[_i].y), \
                              f2tf(stB[_i].z), f2tf(stB[_i].w)); \
        *(uint4*)&Bs[buf][_r * 32 + 4 * (_c4 ^ (_r & 7))] = _u; \
    } \
} while (0)

    LDG_CHUNK(0);
    STS_CHUNK(0);
    __syncthreads();

    for (int c = 0; c < NCHUNK; c++) {
        const int buf = c & 1;
        if (c + 1 < NCHUNK) LDG_CHUNK(c + 1);

        const uint32_t* Ab = As[buf];
        const uint32_t* Bb = Bs[buf];
#pragma unroll
        for (int s = 0; s < 4; s++) {
            const int pk0 = (s * 8 + t) ^ (g << 2);
            const int pk1 = pk0 ^ 4;
            uint32_t af[2][4], bf[4][2];
#pragma unroll
            for (int mt = 0; mt < 2; mt++) {
                int r0 = wm * 32 + mt * 16 + g;
                af[mt][0] = Ab[r0 * 32 + pk0];
                af[mt][1] = Ab[(r0 + 8) * 32 + pk0];
                af[mt][2] = Ab[r0 * 32 + pk1];
                af[mt][3] = Ab[(r0 + 8) * 32 + pk1];
            }
#pragma unroll
            for (int nt = 0; nt < 4; nt++) {
                int nr = wn * 32 + nt * 8 + g;
                bf[nt][0] = Bb[nr * 32 + pk0];
                bf[nt][1] = Bb[nr * 32 + pk1];
            }
#pragma unroll
            for (int mt = 0; mt < 2; mt++)
#pragma unroll
                for (int nt = 0; nt < 4; nt++)
                    MMA_TF32(acc[mt][nt], af[mt], bf[nt]);
        }

        if (c + 1 < NCHUNK) STS_CHUNK(buf ^ 1);
        __syncthreads();
    }

    const int h = n0 >> 6;
    float* qkv = (mode == 0) ? g_q : (mode == 1) ? g_k : g_v;
    const float sc = (mode == 0) ? 0.125f : 1.0f;
#pragma unroll
    for (int mt = 0; mt < 2; mt++) {
#pragma unroll
        for (int half = 0; half < 2; half++) {
            int row = m0 + wm * 32 + mt * 16 + g + half * 8;
            int b = row / SS, sx = row % SS;
            float* dst0 = (mode == 3)
                ? (outp + (size_t)row * DD)
                : (qkv + (size_t)((b * HH + h) * SS + sx) * HDIM - n0);
#pragma unroll
            for (int nt = 0; nt < 4; nt++) {
                int n = n0 + wn * 32 + nt * 8 + 2 * t;
                float2 bv = *(const float2*)&bias[n];
                float2 r;
                r.x = acc[mt][nt][half * 2 + 0] + bv.x;
                r.y = acc[mt][nt][half * 2 + 1] + bv.y;
                if (mode != 3) {
                    r.x = __uint_as_float(f2tf(r.x * sc));
                    r.y = __uint_as_float(f2tf(r.y * sc));
                }
                *(float2*)(dst0 + n) = r;
            }
        }
    }
}

// ============================================================================
// Tensor-core flash attention, cp.async double-buffered + ldmatrix fragments.
// Smem (dynamic, 104448 B):
//   buf{0,1} @ word 0 / 8704 : each K(64x68) | V(64x68)
//   P slabs  @ word 17408    : 8 warps x (16 x 68)  (warp-private)
// ============================================================================
#define KVP 68              // smem pitch (words)
#define BUFW 8704           // words per KV buffer (2 * 64 * 68)
#define PBASE 17408         // word offset of P slabs
#define NKT 25              // ceil(1568/64); 1568 = 24*64 + 32
#define ATTN_SMEM ((PBASE + 8 * 1088) * 4)   // 104448 B

__global__ void __launch_bounds__(256, 2) attn_mma()
{
    extern __shared__ __align__(16) uint32_t smw[];
    const uint32_t sbase = smem_u32(smw);

    const int b  = blockIdx.z;
    const int h  = blockIdx.y;
    const int q0 = blockIdx.x * 128;
    const int tid = threadIdx.x;
    const int w   = tid >> 5;
    const int lid = tid & 31;
    const int g   = lid >> 2;
    const int t   = lid & 3;
    const int tau = lid >> 3;          // ldmatrix matrix index
    const int lrw = lid & 7;           // ldmatrix row within matrix

    const float* qb = g_q + (size_t)(b * HH + h) * SS * HDIM;
    const float* kb = g_k + (size_t)(b * HH + h) * SS * HDIM;
    const float* vb = g_v + (size_t)(b * HH + h) * SS * HDIM;

    // per-thread cp.async coordinates
    const int cr  = tid >> 4;
    const int cc4 = tid & 15;

#define CPA_KV(kt_, buf_) do { \
    _Pragma("unroll") \
    for (int _i = 0; _i < 4; _i++) { \
        int _r = cr + _i * 16; \
        int _kr = (kt_) * 64 + _r; if (_kr >= SS) _kr = SS - 1; \
        uint32_t _d = sbase + ((buf_) * BUFW + _r * KVP + cc4 * 4) * 4; \
        cp_async16(_d,            kb + (size_t)_kr * HDIM + cc4 * 4); \
        cp_async16(_d + 4352 * 4, vb + (size_t)_kr * HDIM + cc4 * 4); \
    } \
} while (0)

    // ---- stage Q (128x64) into buf1 via cp.async; KV0 into buf0 ----
#pragma unroll
    for (int i = 0; i < 8; i++) {
        int r = cr + i * 16;
        int qr = q0 + r; if (qr >= SS) qr = SS - 1;
        uint32_t d = sbase + (BUFW + r * KVP + cc4 * 4) * 4;
        cp_async16(d, qb + (size_t)qr * HDIM + cc4 * 4);
    }
    CP_COMMIT();                      // group: Q
    CPA_KV(0, 0);
    CP_COMMIT();                      // group: KV0
    CP_WAIT(1);                       // Q done
    __syncthreads();

    // ---- Q fragments to registers ----
    uint32_t qf[8][4];
    {
        const uint32_t* Qb = smw + BUFW;
        const int r0 = (w * 16 + g) * KVP;
        const int r8 = r0 + 8 * KVP;
#pragma unroll
        for (int s = 0; s < 8; s++) {
            qf[s][0] = Qb[r0 + 8 * s + t];
            qf[s][1] = Qb[r8 + 8 * s + t];
            qf[s][2] = Qb[r0 + 8 * s + t + 4];
            qf[s][3] = Qb[r8 + 8 * s + t + 4];
        }
    }
    __syncthreads();                  // qf reads done before buf1 reuse
    CPA_KV(1, 1);
    CP_COMMIT();                      // group: KV1

    // ldmatrix per-thread address components (byte offsets)
    // K tiles, instr i: matrices (nt=2i,j=0),(2i,j=1),(2i+1,j=0),(2i+1,j=1)
    //   lane supplies row lrw of matrix tau:
    //   nt_sub = tau>>1, j = tau&1 ->  row_in_K = 8*(tau>>1)+lrw (+16 per i)
    const uint32_t k_off =
        (uint32_t)(((8 * (tau >> 1) + lrw) * KVP + 4 * (tau & 1)) * 4);
    // P tiles (A-frag), per s: matrices (rows0-7,j0),(rows8-15,j0),(r0-7,j1),(r8-15,j1)
    const uint32_t pw = sbase + (uint32_t)((PBASE + w * 1088) * 4);
    const uint32_t p_off =
        (uint32_t)(((lrw + 8 * (tau & 1)) * KVP + 4 * (tau >> 1)) * 4);
    uint32_t* Pw = smw + PBASE + w * 1088;

    float m0v = -1e30f, m1v = -1e30f, l0 = 0.f, l1 = 0.f;
    float ao[8][4];
#pragma unroll
    for (int nt = 0; nt < 8; nt++)
#pragma unroll
        for (int j = 0; j < 4; j++) ao[nt][j] = 0.f;

    for (int kt = 0; kt < NKT; kt++) {
        if (kt == NKT - 1) CP_WAIT(0); else CP_WAIT(1);
        __syncthreads();

        const uint32_t kbuf = (uint32_t)((kt & 1) * BUFW * 4);
        const uint32_t ka = sbase + kbuf + k_off;
        const uint32_t* Vb = smw + (kt & 1) * BUFW + 4352;

        // ---- S = Q K^T : K fragments via ldmatrix ----
        float sf[8][4];
#pragma unroll
        for (int nt = 0; nt < 8; nt++)
#pragma unroll
            for (int j = 0; j < 4; j++) sf[nt][j] = 0.f;
#pragma unroll
        for (int s = 0; s < 8; s++) {
            uint32_t kf[16];
            LDMX4(kf[0],  kf[1],  kf[2],  kf[3],  ka + s * 32);
            LDMX4(kf[4],  kf[5],  kf[6],  kf[7],  ka + 4352 + s * 32);
            LDMX4(kf[8],  kf[9],  kf[10], kf[11], ka + 8704 + s * 32);
            LDMX4(kf[12], kf[13], kf[14], kf[15], ka + 13056 + s * 32);
#pragma unroll
            for (int nt = 0; nt < 8; nt++)
                MMA_TF32(sf[nt], qf[s], &kf[2 * nt]);
        }
        if (kt == NKT - 1) {          // 1568 = 24*64+32: n-tiles 4..7 invalid
#pragma unroll
            for (int nt = 4; nt < 8; nt++) {
                sf[nt][0] = -1e30f; sf[nt][1] = -1e30f;
                sf[nt][2] = -1e30f; sf[nt][3] = -1e30f;
            }
        }

        // ---- online softmax (rows g, g+8; quad reduce over t) ----
        float mx0 = -1e30f, mx1 = -1e30f;
#pragma unroll
        for (int nt = 0; nt < 8; nt++) {
            mx0 = fmaxf(mx0, fmaxf(sf[nt][0], sf[nt][1]));
            mx1 = fmaxf(mx1, fmaxf(sf[nt][2], sf[nt][3]));
        }
        mx0 = fmaxf(mx0, __shfl_xor_sync(0xffffffffu, mx0, 1));
        mx0 = fmaxf(mx0, __shfl_xor_sync(0xffffffffu, mx0, 2));
        mx1 = fmaxf(mx1, __shfl_xor_sync(0xffffffffu, mx1, 1));
        mx1 = fmaxf(mx1, __shfl_xor_sync(0xffffffffu, mx1, 2));
        const float mn0 = fmaxf(m0v, mx0);
        const float mn1 = fmaxf(m1v, mx1);
        const float a0 = __expf(m0v - mn0);
        const float a1 = __expf(m1v - mn1);
        m0v = mn0; m1v = mn1;

        float s0 = 0.f, s1 = 0.f;
#pragma unroll
        for (int nt = 0; nt < 8; nt++) {   // exp -> P slab (warp-private)
            float e0 = __expf(sf[nt][0] - mn0);
            float e1 = __expf(sf[nt][1] - mn0);
            float e2 = __expf(sf[nt][2] - mn1);
            float e3 = __expf(sf[nt][3] - mn1);
            s0 += e0 + e1; s1 += e2 + e3;
            *(uint2*)&Pw[g * KVP + 8 * nt + 2 * t] =
                make_uint2(f2tf(e0), f2tf(e1));
            *(uint2*)&Pw[(g + 8) * KVP + 8 * nt + 2 * t] =
                make_uint2(f2tf(e2), f2tf(e3));
        }
        s0 += __shfl_xor_sync(0xffffffffu, s0, 1);
        s0 += __shfl_xor_sync(0xffffffffu, s0, 2);
        s1 += __shfl_xor_sync(0xffffffffu, s1, 1);
        s1 += __shfl_xor_sync(0xffffffffu, s1, 2);
        l0 = l0 * a0 + s0;
        l1 = l1 * a1 + s1;
#pragma unroll
        for (int nt = 0; nt < 8; nt++) {
            ao[nt][0] *= a0; ao[nt][1] *= a0;
            ao[nt][2] *= a1; ao[nt][3] *= a1;
        }
        __syncwarp();                 // P stores visible warp-wide

        // ---- O += P V : A-frags via ldmatrix from P slab ----
#pragma unroll
        for (int s = 0; s < 8; s++) {
            uint32_t af[4];
            LDMX4(af[0], af[1], af[2], af[3], pw + p_off + s * 32);
            const int rb0 = (8 * s + t) * KVP + g;
#pragma unroll
            for (int nt = 0; nt < 8; nt++) {
                uint32_t bf[2];
                bf[0] = Vb[rb0 + 8 * nt];
                bf[1] = Vb[rb0 + 8 * nt + 4 * KVP];
                MMA_TF32(ao[nt], af, bf);
            }
        }
        __syncthreads();
        if (kt + 2 < NKT) { CPA_KV(kt + 2, kt & 1); CP_COMMIT(); }
    }

    // ---- epilogue: normalize, write ctx [B,S,D] ----
    const float i0 = 1.f / l0;
    const float i1 = 1.f / l1;
    const int qg = q0 + w * 16 + g;
    if (qg < SS) {
        float* row = g_ctx + (size_t)(b * SS + qg) * DD + h * HDIM;
#pragma unroll
        for (int nt = 0; nt < 8; nt++) {
            float2 r; r.x = ao[nt][0] * i0; r.y = ao[nt][1] * i0;
            *(float2*)&row[nt * 8 + 2 * t] = r;
        }
    }
    if (qg + 8 < SS) {
        float* row = g_ctx + (size_t)(b * SS + qg + 8) * DD + h * HDIM;
#pragma unroll
        for (int nt = 0; nt < 8; nt++) {
            float2 r; r.x = ao[nt][2] * i1; r.y = ao[nt][3] * i1;
            *(float2*)&row[nt * 8 + 2 * t] = r;
        }
    }
}

// ============================================================================
extern "C" void kernel_launch(void* const* d_in, const int* in_sizes, int n_in,
                              void* d_out, int out_size)
{
    const float* x  = (const float*)d_in[0];
    const float* Wq = (const float*)d_in[1];
    const float* bq = (const float*)d_in[2];
    const float* Wk = (const float*)d_in[3];
    const float* bk = (const float*)d_in[4];
    const float* Wv = (const float*)d_in[5];
    const float* bv = (const float*)d_in[6];
    const float* Wp = (const float*)d_in[7];
    const float* bp = (const float*)d_in[8];
    float* out = (float*)d_out;

    cudaFuncSetAttribute(attn_mma, cudaFuncAttributeMaxDynamicSharedMemorySize,
                         ATTN_SMEM);

    dim3 gg(DD / 64, MTOT / 128);   // 16 x 49
    gemm_tf32<<<gg, 256>>>(x, Wq, bq, nullptr, 0);
    gemm_tf32<<<gg, 256>>>(x, Wk, bk, nullptr, 1);
    gemm_tf32<<<gg, 256>>>(x, Wv, bv, nullptr, 2);

    dim3 ga((SS + 127) / 128, HH, BB);  // 13 x 16 x 4
    attn_mma<<<ga, 256, ATTN_SMEM>>>();

    gemm_tf32<<<gg, 256>>>(nullptr, Wp, bp, out, 3);
}

// round 14
// speedup vs baseline: 2.1610x; 1.1302x over previous
#include <cuda_runtime.h>
#include <cstdint>

#define BB   4
#define SS   1568
#define DD   1024
#define HH   16
#define HDIM 64
#define MTOT (BB*SS)          // 6272

// -------- scratch (no allocation allowed; __device__ globals) --------
__device__ float g_q[BB*HH*SS*HDIM];   // tf32-rounded, 0.125-scaled Q
__device__ float g_k[BB*HH*SS*HDIM];   // tf32-rounded K
__device__ float g_v[BB*HH*SS*HDIM];   // tf32-rounded V
__device__ float g_ctx[MTOT*DD];       // tf32-rounded ctx
__device__ float g_xr[MTOT*DD];        // tf32-rounded hidden_states
__device__ float g_wr[4*DD*DD];        // tf32-rounded Wq|Wk|Wv|Wp

// ============================================================================
// tf32 / async helpers (sm_80-class PTX — compiles under compute_103)
// ============================================================================
__device__ __forceinline__ uint32_t f2tf(float f) {
    uint32_t u;
    asm("cvt.rna.tf32.f32 %0, %1;" : "=r"(u) : "f"(f));
    return u;
}
__device__ __forceinline__ uint32_t smem_u32(const void* p) {
    uint32_t a;
    asm("{ .reg .u64 t; cvta.to.shared.u64 t, %1; cvt.u32.u64 %0, t; }"
        : "=r"(a) : "l"(p));
    return a;
}
__device__ __forceinline__ void cp_async16(uint32_t dst, const void* src) {
    asm volatile("cp.async.cg.shared.global [%0], [%1], 16;"
                 :: "r"(dst), "l"(src) : "memory");
}
#define CP_COMMIT() asm volatile("cp.async.commit_group;" ::: "memory")
#define CP_WAIT(n)  asm volatile("cp.async.wait_group %0;" :: "n"(n) : "memory")

#define MMA_TF32(c, a, b) \
    asm volatile("mma.sync.aligned.m16n8k8.row.col.f32.tf32.tf32.f32 " \
        "{%0,%1,%2,%3}, {%4,%5,%6,%7}, {%8,%9}, {%0,%1,%2,%3};" \
        : "+f"((c)[0]), "+f"((c)[1]), "+f"((c)[2]), "+f"((c)[3]) \
        : "r"((a)[0]), "r"((a)[1]), "r"((a)[2]), "r"((a)[3]), \
          "r"((b)[0]), "r"((b)[1]))

#define LDMX4(r0, r1, r2, r3, addr) \
    asm volatile("ldmatrix.sync.aligned.m8n8.x4.shared.b16 {%0,%1,%2,%3}, [%4];" \
        : "=r"(r0), "=r"(r1), "=r"(r2), "=r"(r3) : "r"(addr))

// ============================================================================
// Pre-round fp32 -> tf32 bits (vectorized elementwise)
// ============================================================================
__global__ void __launch_bounds__(256) round_tf32(
    const float* __restrict__ src, float* __restrict__ dst, int n4)
{
    int i = blockIdx.x * blockDim.x + threadIdx.x;
    if (i < n4) {
        float4 v = *(const float4*)(src + 4 * (size_t)i);
        uint4 u = make_uint4(f2tf(v.x), f2tf(v.y), f2tf(v.z), f2tf(v.w));
        *(uint4*)(dst + 4 * (size_t)i) = u;
    }
}

// ============================================================================
// tf32 tensor-core GEMM, 4-stage cp.async pipeline on pre-rounded operands.
// C[m,n] = sum_k A[m,k]*W[n,k] + bias[n].  BM=128, BN=64, BK=32.
// Smem stage (words): A 128x32 @ +0, B 64x32 @ +4096; XOR swizzle
// word_off = r*32 + 4*(c4 ^ (r&7))  (identical fragment indexing to R9-R12).
//   mode 0/1/2: A = g_xr, write g_q/g_k/g_v tf32-rounded (+bias; Q *0.125)
//   mode 3:     A = g_ctx, write outp raw fp32
// ============================================================================
#define NCHUNK 32    // 1024 / 32
#define GSTW   6144  // words per stage
#define GEMM_SMEM (4 * GSTW * 4)   // 98304 B

__global__ void __launch_bounds__(256, 2) gemm_tf32(
    const float* __restrict__ Wbase,
    const float* __restrict__ bias, float* __restrict__ outp, int mode)
{
    extern __shared__ __align__(16) uint32_t smw[];
    const uint32_t sbase = smem_u32(smw);

    const float* A = (mode == 3) ? g_ctx : g_xr;
    const int tid = threadIdx.x;
    const int wid = tid >> 5;
    const int lid = tid & 31;
    const int wm  = wid >> 1;
    const int wn  = wid & 1;
    const int g   = lid >> 2;
    const int t   = lid & 3;

    const int m0 = blockIdx.y * 128;
    const int n0 = blockIdx.x * 64;

    const float* aP = A + (size_t)m0 * DD;
    const float* wP = Wbase + (size_t)n0 * DD;

    float acc[2][4][4];
#pragma unroll
    for (int mt = 0; mt < 2; mt++)
#pragma unroll
        for (int nt = 0; nt < 4; nt++)
#pragma unroll
            for (int j = 0; j < 4; j++) acc[mt][nt][j] = 0.f;

#define GCPA(kc, stg) do { \
    uint32_t _sb = sbase + (uint32_t)(stg) * (GSTW * 4); \
    _Pragma("unroll") \
    for (int _i = 0; _i < 4; _i++) { \
        int _idx = tid + _i * 256; \
        int _r = _idx >> 3, _c4 = _idx & 7; \
        cp_async16(_sb + (_r * 32 + 4 * (_c4 ^ (_r & 7))) * 4, \
                   aP + (size_t)_r * DD + (kc) * 32 + _c4 * 4); \
    } \
    _Pragma("unroll") \
    for (int _i = 0; _i < 2; _i++) { \
        int _idx = tid + _i * 256; \
        int _r = _idx >> 3, _c4 = _idx & 7; \
        cp_async16(_sb + 16384 + (_r * 32 + 4 * (_c4 ^ (_r & 7))) * 4, \
                   wP + (size_t)_r * DD + (kc) * 32 + _c4 * 4); \
    } \
    CP_COMMIT(); \
} while (0)

    GCPA(0, 0);
    GCPA(1, 1);
    GCPA(2, 2);

    for (int c = 0; c < NCHUNK; c++) {
        if (c < 30)      CP_WAIT(2);
        else if (c == 30) CP_WAIT(1);
        else              CP_WAIT(0);
        __syncthreads();
        if (c + 3 < NCHUNK) GCPA(c + 3, (c + 3) & 3);

        const uint32_t* Ab = smw + (c & 3) * GSTW;
        const uint32_t* Bb = Ab + 4096;
#pragma unroll
        for (int s = 0; s < 4; s++) {
            const int pk0 = (s * 8 + t) ^ (g << 2);
            const int pk1 = pk0 ^ 4;
            uint32_t af[2][4], bf[4][2];
#pragma unroll
            for (int mt = 0; mt < 2; mt++) {
                int r0 = wm * 32 + mt * 16 + g;
                af[mt][0] = Ab[r0 * 32 + pk0];
                af[mt][1] = Ab[(r0 + 8) * 32 + pk0];
                af[mt][2] = Ab[r0 * 32 + pk1];
                af[mt][3] = Ab[(r0 + 8) * 32 + pk1];
            }
#pragma unroll
            for (int nt = 0; nt < 4; nt++) {
                int nr = wn * 32 + nt * 8 + g;
                bf[nt][0] = Bb[nr * 32 + pk0];
                bf[nt][1] = Bb[nr * 32 + pk1];
            }
#pragma unroll
            for (int mt = 0; mt < 2; mt++)
#pragma unroll
                for (int nt = 0; nt < 4; nt++)
                    MMA_TF32(acc[mt][nt], af[mt], bf[nt]);
        }
    }

    const int h = n0 >> 6;
    float* qkv = (mode == 0) ? g_q : (mode == 1) ? g_k : g_v;
    const float sc = (mode == 0) ? 0.125f : 1.0f;
#pragma unroll
    for (int mt = 0; mt < 2; mt++) {
#pragma unroll
        for (int half = 0; half < 2; half++) {
            int row = m0 + wm * 32 + mt * 16 + g + half * 8;
            int b = row / SS, sx = row % SS;
            float* dst0 = (mode == 3)
                ? (outp + (size_t)row * DD)
                : (qkv + (size_t)((b * HH + h) * SS + sx) * HDIM - n0);
#pragma unroll
            for (int nt = 0; nt < 4; nt++) {
                int n = n0 + wn * 32 + nt * 8 + 2 * t;
                float2 bv = *(const float2*)&bias[n];
                float2 r;
                r.x = acc[mt][nt][half * 2 + 0] + bv.x;
                r.y = acc[mt][nt][half * 2 + 1] + bv.y;
                if (mode != 3) {
                    r.x = __uint_as_float(f2tf(r.x * sc));
                    r.y = __uint_as_float(f2tf(r.y * sc));
                }
                *(float2*)(dst0 + n) = r;
            }
        }
    }
}

// ============================================================================
// Tensor-core flash attention (unchanged from R12 except: ctx written
// tf32-rounded, since its only consumer is the mode-3 GEMM).
// ============================================================================
#define KVP 68              // smem pitch (words)
#define BUFW 8704           // words per KV buffer (2 * 64 * 68)
#define PBASE 17408         // word offset of P slabs
#define NKT 25              // ceil(1568/64); 1568 = 24*64 + 32
#define ATTN_SMEM ((PBASE + 8 * 1088) * 4)   // 104448 B

__global__ void __launch_bounds__(256, 2) attn_mma()
{
    extern __shared__ __align__(16) uint32_t smw[];
    const uint32_t sbase = smem_u32(smw);

    const int b  = blockIdx.z;
    const int h  = blockIdx.y;
    const int q0 = blockIdx.x * 128;
    const int tid = threadIdx.x;
    const int w   = tid >> 5;
    const int lid = tid & 31;
    const int g   = lid >> 2;
    const int t   = lid & 3;
    const int tau = lid >> 3;
    const int lrw = lid & 7;

    const float* qb = g_q + (size_t)(b * HH + h) * SS * HDIM;
    const float* kb = g_k + (size_t)(b * HH + h) * SS * HDIM;
    const float* vb = g_v + (size_t)(b * HH + h) * SS * HDIM;

    const int cr  = tid >> 4;
    const int cc4 = tid & 15;

#define CPA_KV(kt_, buf_) do { \
    _Pragma("unroll") \
    for (int _i = 0; _i < 4; _i++) { \
        int _r = cr + _i * 16; \
        int _kr = (kt_) * 64 + _r; if (_kr >= SS) _kr = SS - 1; \
        uint32_t _d = sbase + ((buf_) * BUFW + _r * KVP + cc4 * 4) * 4; \
        cp_async16(_d,            kb + (size_t)_kr * HDIM + cc4 * 4); \
        cp_async16(_d + 4352 * 4, vb + (size_t)_kr * HDIM + cc4 * 4); \
    } \
} while (0)

#pragma unroll
    for (int i = 0; i < 8; i++) {
        int r = cr + i * 16;
        int qr = q0 + r; if (qr >= SS) qr = SS - 1;
        uint32_t d = sbase + (BUFW + r * KVP + cc4 * 4) * 4;
        cp_async16(d, qb + (size_t)qr * HDIM + cc4 * 4);
    }
    CP_COMMIT();
    CPA_KV(0, 0);
    CP_COMMIT();
    CP_WAIT(1);
    __syncthreads();

    uint32_t qf[8][4];
    {
        const uint32_t* Qb = smw + BUFW;
        const int r0 = (w * 16 + g) * KVP;
        const int r8 = r0 + 8 * KVP;
#pragma unroll
        for (int s = 0; s < 8; s++) {
            qf[s][0] = Qb[r0 + 8 * s + t];
            qf[s][1] = Qb[r8 + 8 * s + t];
            qf[s][2] = Qb[r0 + 8 * s + t + 4];
            qf[s][3] = Qb[r8 + 8 * s + t + 4];
        }
    }
    __syncthreads();
    CPA_KV(1, 1);
    CP_COMMIT();

    const uint32_t k_off =
        (uint32_t)(((8 * (tau >> 1) + lrw) * KVP + 4 * (tau & 1)) * 4);
    const uint32_t pw = sbase + (uint32_t)((PBASE + w * 1088) * 4);
    const uint32_t p_off =
        (uint32_t)(((lrw + 8 * (tau & 1)) * KVP + 4 * (tau >> 1)) * 4);
    uint32_t* Pw = smw + PBASE + w * 1088;

    float m0v = -1e30f, m1v = -1e30f, l0 = 0.f, l1 = 0.f;
    float ao[8][4];
#pragma unroll
    for (int nt = 0; nt < 8; nt++)
#pragma unroll
        for (int j = 0; j < 4; j++) ao[nt][j] = 0.f;

    for (int kt = 0; kt < NKT; kt++) {
        if (kt == NKT - 1) CP_WAIT(0); else CP_WAIT(1);
        __syncthreads();

        const uint32_t kbuf = (uint32_t)((kt & 1) * BUFW * 4);
        const uint32_t ka = sbase + kbuf + k_off;
        const uint32_t* Vb = smw + (kt & 1) * BUFW + 4352;

        float sf[8][4];
#pragma unroll
        for (int nt = 0; nt < 8; nt++)
#pragma unroll
            for (int j = 0; j < 4; j++) sf[nt][j] = 0.f;
#pragma unroll
        for (int s = 0; s < 8; s++) {
            uint32_t kf[16];
            LDMX4(kf[0],  kf[1],  kf[2],  kf[3],  ka + s * 32);
            LDMX4(kf[4],  kf[5],  kf[6],  kf[7],  ka + 4352 + s * 32);
            LDMX4(kf[8],  kf[9],  kf[10], kf[11], ka + 8704 + s * 32);
            LDMX4(kf[12], kf[13], kf[14], kf[15], ka + 13056 + s * 32);
#pragma unroll
            for (int nt = 0; nt < 8; nt++)
                MMA_TF32(sf[nt], qf[s], &kf[2 * nt]);
        }
        if (kt == NKT - 1) {
#pragma unroll
            for (int nt = 4; nt < 8; nt++) {
                sf[nt][0] = -1e30f; sf[nt][1] = -1e30f;
                sf[nt][2] = -1e30f; sf[nt][3] = -1e30f;
            }
        }

        float mx0 = -1e30f, mx1 = -1e30f;
#pragma unroll
        for (int nt = 0; nt < 8; nt++) {
            mx0 = fmaxf(mx0, fmaxf(sf[nt][0], sf[nt][1]));
            mx1 = fmaxf(mx1, fmaxf(sf[nt][2], sf[nt][3]));
        }
        mx0 = fmaxf(mx0, __shfl_xor_sync(0xffffffffu, mx0, 1));
        mx0 = fmaxf(mx0, __shfl_xor_sync(0xffffffffu, mx0, 2));
        mx1 = fmaxf(mx1, __shfl_xor_sync(0xffffffffu, mx1, 1));
        mx1 = fmaxf(mx1, __shfl_xor_sync(0xffffffffu, mx1, 2));
        const float mn0 = fmaxf(m0v, mx0);
        const float mn1 = fmaxf(m1v, mx1);
        const float a0 = __expf(m0v - mn0);
        const float a1 = __expf(m1v - mn1);
        m0v = mn0; m1v = mn1;

        float s0 = 0.f, s1 = 0.f;
#pragma unroll
        for (int nt = 0; nt < 8; nt++) {
            float e0 = __expf(sf[nt][0] - mn0);
            float e1 = __expf(sf[nt][1] - mn0);
            float e2 = __expf(sf[nt][2] - mn1);
            float e3 = __expf(sf[nt][3] - mn1);
            s0 += e0 + e1; s1 += e2 + e3;
            *(uint2*)&Pw[g * KVP + 8 * nt + 2 * t] =
                make_uint2(f2tf(e0), f2tf(e1));
            *(uint2*)&Pw[(g + 8) * KVP + 8 * nt + 2 * t] =
                make_uint2(f2tf(e2), f2tf(e3));
        }
        s0 += __shfl_xor_sync(0xffffffffu, s0, 1);
        s0 += __shfl_xor_sync(0xffffffffu, s0, 2);
        s1 += __shfl_xor_sync(0xffffffffu, s1, 1);
        s1 += __shfl_xor_sync(0xffffffffu, s1, 2);
        l0 = l0 * a0 + s0;
        l1 = l1 * a1 + s1;
#pragma unroll
        for (int nt = 0; nt < 8; nt++) {
            ao[nt][0] *= a0; ao[nt][1] *= a0;
            ao[nt][2] *= a1; ao[nt][3] *= a1;
        }
        __syncwarp();

#pragma unroll
        for (int s = 0; s < 8; s++) {
            uint32_t af[4];
            LDMX4(af[0], af[1], af[2], af[3], pw + p_off + s * 32);
            const int rb0 = (8 * s + t) * KVP + g;
#pragma unroll
            for (int nt = 0; nt < 8; nt++) {
                uint32_t bf[2];
                bf[0] = Vb[rb0 + 8 * nt];
                bf[1] = Vb[rb0 + 8 * nt + 4 * KVP];
                MMA_TF32(ao[nt], af, bf);
            }
        }
        __syncthreads();
        if (kt + 2 < NKT) { CPA_KV(kt + 2, kt & 1); CP_COMMIT(); }
    }

    // epilogue: normalize, tf32-round (feeds mode-3 GEMM), write ctx [B,S,D]
    const float i0 = 1.f / l0;
    const float i1 = 1.f / l1;
    const int qg = q0 + w * 16 + g;
    if (qg < SS) {
        float* row = g_ctx + (size_t)(b * SS + qg) * DD + h * HDIM;
#pragma unroll
        for (int nt = 0; nt < 8; nt++) {
            uint2 r = make_uint2(f2tf(ao[nt][0] * i0), f2tf(ao[nt][1] * i0));
            *(uint2*)&row[nt * 8 + 2 * t] = r;
        }
    }
    if (qg + 8 < SS) {
        float* row = g_ctx + (size_t)(b * SS + qg + 8) * DD + h * HDIM;
#pragma unroll
        for (int nt = 0; nt < 8; nt++) {
            uint2 r = make_uint2(f2tf(ao[nt][2] * i1), f2tf(ao[nt][3] * i1));
            *(uint2*)&row[nt * 8 + 2 * t] = r;
        }
    }
}

// ============================================================================
extern "C" void kernel_launch(void* const* d_in, const int* in_sizes, int n_in,
                              void* d_out, int out_size)
{
    const float* x  = (const float*)d_in[0];
    const float* Wq = (const float*)d_in[1];
    const float* bq = (const float*)d_in[2];
    const float* Wk = (const float*)d_in[3];
    const float* bk = (const float*)d_in[4];
    const float* Wv = (const float*)d_in[5];
    const float* bv = (const float*)d_in[6];
    const float* Wp = (const float*)d_in[7];
    const float* bp = (const float*)d_in[8];
    float* out = (float*)d_out;

    cudaFuncSetAttribute(gemm_tf32, cudaFuncAttributeMaxDynamicSharedMemorySize,
                         GEMM_SMEM);
    cudaFuncSetAttribute(attn_mma, cudaFuncAttributeMaxDynamicSharedMemorySize,
                         ATTN_SMEM);

    // resolve device-global addresses (host-side, graph-capturable)
    float *xr, *wr;
    cudaGetSymbolAddress((void**)&xr, g_xr);
    cudaGetSymbolAddress((void**)&wr, g_wr);

    // pre-round operands to tf32
    round_tf32<<<(MTOT * DD / 4 + 255) / 256, 256>>>(x, xr, MTOT * DD / 4);
    round_tf32<<<(DD * DD / 4 + 255) / 256, 256>>>(Wq, wr + 0 * DD * DD, DD * DD / 4);
    round_tf32<<<(DD * DD / 4 + 255) / 256, 256>>>(Wk, wr + 1 * DD * DD, DD * DD / 4);
    round_tf32<<<(DD * DD / 4 + 255) / 256, 256>>>(Wv, wr + 2 * DD * DD, DD * DD / 4);
    round_tf32<<<(DD * DD / 4 + 255) / 256, 256>>>(Wp, wr + 3 * DD * DD, DD * DD / 4);

    dim3 gg(DD / 64, MTOT / 128);   // 16 x 49
    gemm_tf32<<<gg, 256, GEMM_SMEM>>>(wr + 0 * DD * DD, bq, nullptr, 0);
    gemm_tf32<<<gg, 256, GEMM_SMEM>>>(wr + 1 * DD * DD, bk, nullptr, 1);
    gemm_tf32<<<gg, 256, GEMM_SMEM>>>(wr + 2 * DD * DD, bv, nullptr, 2);

    dim3 ga((SS + 127) / 128, HH, BB);  // 13 x 16 x 4
    attn_mma<<<ga, 256, ATTN_SMEM>>>();

    gemm_tf32<<<gg, 256, GEMM_SMEM>>>(wr + 3 * DD * DD, bp, out, 3);
}

// round 15
// speedup vs baseline: 2.3004x; 1.0645x over previous
#include <cuda_runtime.h>
#include <cstdint>

#define BB   4
#define SS   1568
#define DD   1024
#define HH   16
#define HDIM 64
#define MTOT (BB*SS)          // 6272

// -------- scratch (no allocation allowed; __device__ globals) --------
__device__ float g_q[BB*HH*SS*HDIM];   // tf32-rounded, 0.125-scaled Q
__device__ float g_k[BB*HH*SS*HDIM];   // tf32-rounded K
__device__ float g_v[BB*HH*SS*HDIM];   // tf32-rounded V
__device__ float g_ctx[MTOT*DD];       // tf32-rounded ctx
__device__ float g_xr[MTOT*DD];        // tf32-rounded hidden_states
__device__ float g_wr[4*DD*DD];        // tf32-rounded Wq|Wk|Wv|Wp

// ============================================================================
// tf32 / async helpers (sm_80-class PTX — compiles under compute_103)
// ============================================================================
__device__ __forceinline__ uint32_t f2tf(float f) {
    uint32_t u;
    asm("cvt.rna.tf32.f32 %0, %1;" : "=r"(u) : "f"(f));
    return u;
}
__device__ __forceinline__ uint32_t smem_u32(const void* p) {
    uint32_t a;
    asm("{ .reg .u64 t; cvta.to.shared.u64 t, %1; cvt.u32.u64 %0, t; }"
        : "=r"(a) : "l"(p));
    return a;
}
__device__ __forceinline__ void cp_async16(uint32_t dst, const void* src) {
    asm volatile("cp.async.cg.shared.global [%0], [%1], 16;"
                 :: "r"(dst), "l"(src) : "memory");
}
#define CP_COMMIT() asm volatile("cp.async.commit_group;" ::: "memory")
#define CP_WAIT(n)  asm volatile("cp.async.wait_group %0;" :: "n"(n) : "memory")

#define MMA_TF32(c, a, b) \
    asm volatile("mma.sync.aligned.m16n8k8.row.col.f32.tf32.tf32.f32 " \
        "{%0,%1,%2,%3}, {%4,%5,%6,%7}, {%8,%9}, {%0,%1,%2,%3};" \
        : "+f"((c)[0]), "+f"((c)[1]), "+f"((c)[2]), "+f"((c)[3]) \
        : "r"((a)[0]), "r"((a)[1]), "r"((a)[2]), "r"((a)[3]), \
          "r"((b)[0]), "r"((b)[1]))

#define LDMX4(r0, r1, r2, r3, addr) \
    asm volatile("ldmatrix.sync.aligned.m8n8.x4.shared.b16 {%0,%1,%2,%3}, [%4];" \
        : "=r"(r0), "=r"(r1), "=r"(r2), "=r"(r3) : "r"(addr))

// ============================================================================
// Pre-round fp32 -> tf32 bits
// ============================================================================
__global__ void __launch_bounds__(256) round_tf32(
    const float* __restrict__ src, float* __restrict__ dst, int n4)
{
    int i = blockIdx.x * blockDim.x + threadIdx.x;
    if (i < n4) {
        float4 v = *(const float4*)(src + 4 * (size_t)i);
        uint4 u = make_uint4(f2tf(v.x), f2tf(v.y), f2tf(v.z), f2tf(v.w));
        *(uint4*)(dst + 4 * (size_t)i) = u;
    }
}

// 4 weight matrices in one launch: grid (DD*DD/4/256, 4)
__global__ void __launch_bounds__(256) round_w4(
    const float* __restrict__ w0, const float* __restrict__ w1,
    const float* __restrict__ w2, const float* __restrict__ w3,
    float* __restrict__ dst)
{
    const float* src = (blockIdx.y == 0) ? w0 : (blockIdx.y == 1) ? w1
                     : (blockIdx.y == 2) ? w2 : w3;
    int i = blockIdx.x * blockDim.x + threadIdx.x;   // < DD*DD/4
    float4 v = *(const float4*)(src + 4 * (size_t)i);
    uint4 u = make_uint4(f2tf(v.x), f2tf(v.y), f2tf(v.z), f2tf(v.w));
    *(uint4*)(dst + (size_t)blockIdx.y * DD * DD + 4 * (size_t)i) = u;
}

// ============================================================================
// tf32 tensor-core GEMM, 4-stage cp.async pipeline on pre-rounded operands.
// C[m,n] = sum_k A[m,k]*W[n,k] + bias[n].  BM=128, BN=64, BK=32.
//
// Fused QKV form (outp==nullptr): grid (48, 49).
//   mode = blockIdx.x>>4 (0=Q,1=K,2=V), n0 = (blockIdx.x&15)*64,
//   W = g_wr + mode*DD*DD, bias selected per mode,
//   writes g_q/g_k/g_v tf32-rounded (+bias; Q *0.125).
// Out-proj form (outp!=nullptr): grid (16, 49), mode 3, A = g_ctx,
//   W = g_wr + 3*DD*DD, writes raw fp32.
// ============================================================================
#define NCHUNK 32    // 1024 / 32
#define GSTW   6144  // words per stage
#define GEMM_SMEM (4 * GSTW * 4)   // 98304 B

__global__ void __launch_bounds__(256, 2) gemm_tf32(
    const float* __restrict__ b0p, const float* __restrict__ b1p,
    const float* __restrict__ b2p, float* __restrict__ outp)
{
    extern __shared__ __align__(16) uint32_t smw[];
    const uint32_t sbase = smem_u32(smw);

    const int mode = outp ? 3 : (blockIdx.x >> 4);
    const int n0   = (outp ? blockIdx.x : (blockIdx.x & 15)) * 64;
    const float* A = (mode == 3) ? g_ctx : g_xr;
    const float* bias = (mode == 0) ? b0p : (mode == 1) ? b1p
                      : (mode == 2) ? b2p : b0p;   // mode 3 passes bp as b0p
    const float* Wbase = g_wr + (size_t)mode * DD * DD;

    const int tid = threadIdx.x;
    const int wid = tid >> 5;
    const int lid = tid & 31;
    const int wm  = wid >> 1;
    const int wn  = wid & 1;
    const int g   = lid >> 2;
    const int t   = lid & 3;

    const int m0 = blockIdx.y * 128;

    const float* aP = A + (size_t)m0 * DD;
    const float* wP = Wbase + (size_t)n0 * DD;

    float acc[2][4][4];
#pragma unroll
    for (int mt = 0; mt < 2; mt++)
#pragma unroll
        for (int nt = 0; nt < 4; nt++)
#pragma unroll
            for (int j = 0; j < 4; j++) acc[mt][nt][j] = 0.f;

#define GCPA(kc, stg) do { \
    uint32_t _sb = sbase + (uint32_t)(stg) * (GSTW * 4); \
    _Pragma("unroll") \
    for (int _i = 0; _i < 4; _i++) { \
        int _idx = tid + _i * 256; \
        int _r = _idx >> 3, _c4 = _idx & 7; \
        cp_async16(_sb + (_r * 32 + 4 * (_c4 ^ (_r & 7))) * 4, \
                   aP + (size_t)_r * DD + (kc) * 32 + _c4 * 4); \
    } \
    _Pragma("unroll") \
    for (int _i = 0; _i < 2; _i++) { \
        int _idx = tid + _i * 256; \
        int _r = _idx >> 3, _c4 = _idx & 7; \
        cp_async16(_sb + 16384 + (_r * 32 + 4 * (_c4 ^ (_r & 7))) * 4, \
                   wP + (size_t)_r * DD + (kc) * 32 + _c4 * 4); \
    } \
    CP_COMMIT(); \
} while (0)

    GCPA(0, 0);
    GCPA(1, 1);
    GCPA(2, 2);

    for (int c = 0; c < NCHUNK; c++) {
        if (c < 30)       CP_WAIT(2);
        else if (c == 30) CP_WAIT(1);
        else              CP_WAIT(0);
        __syncthreads();
        if (c + 3 < NCHUNK) GCPA(c + 3, (c + 3) & 3);

        const uint32_t* Ab = smw + (c & 3) * GSTW;
        const uint32_t* Bb = Ab + 4096;
#pragma unroll
        for (int s = 0; s < 4; s++) {
            const int pk0 = (s * 8 + t) ^ (g << 2);
            const int pk1 = pk0 ^ 4;
            uint32_t af[2][4], bf[4][2];
#pragma unroll
            for (int mt = 0; mt < 2; mt++) {
                int r0 = wm * 32 + mt * 16 + g;
                af[mt][0] = Ab[r0 * 32 + pk0];
                af[mt][1] = Ab[(r0 + 8) * 32 + pk0];
                af[mt][2] = Ab[r0 * 32 + pk1];
                af[mt][3] = Ab[(r0 + 8) * 32 + pk1];
            }
#pragma unroll
            for (int nt = 0; nt < 4; nt++) {
                int nr = wn * 32 + nt * 8 + g;
                bf[nt][0] = Bb[nr * 32 + pk0];
                bf[nt][1] = Bb[nr * 32 + pk1];
            }
#pragma unroll
            for (int mt = 0; mt < 2; mt++)
#pragma unroll
                for (int nt = 0; nt < 4; nt++)
                    MMA_TF32(acc[mt][nt], af[mt], bf[nt]);
        }
    }

    const int h = n0 >> 6;
    float* qkv = (mode == 0) ? g_q : (mode == 1) ? g_k : g_v;
    const float sc = (mode == 0) ? 0.125f : 1.0f;
#pragma unroll
    for (int mt = 0; mt < 2; mt++) {
#pragma unroll
        for (int half = 0; half < 2; half++) {
            int row = m0 + wm * 32 + mt * 16 + g + half * 8;
            int b = row / SS, sx = row % SS;
            float* dst0 = (mode == 3)
                ? (outp + (size_t)row * DD)
                : (qkv + (size_t)((b * HH + h) * SS + sx) * HDIM - n0);
#pragma unroll
            for (int nt = 0; nt < 4; nt++) {
                int n = n0 + wn * 32 + nt * 8 + 2 * t;
                float2 bv = *(const float2*)&bias[n - (mode == 3 ? 0 : (mode ? 0 : 0))];
                float2 r;
                r.x = acc[mt][nt][half * 2 + 0] + bv.x;
                r.y = acc[mt][nt][half * 2 + 1] + bv.y;
                if (mode != 3) {
                    r.x = __uint_as_float(f2tf(r.x * sc));
                    r.y = __uint_as_float(f2tf(r.y * sc));
                }
                *(float2*)(dst0 + n) = r;
            }
        }
    }
}

// ============================================================================
// Tensor-core flash attention (byte-identical math to R13).
// ============================================================================
#define KVP 68              // smem pitch (words)
#define BUFW 8704           // words per KV buffer (2 * 64 * 68)
#define PBASE 17408         // word offset of P slabs
#define NKT 25              // ceil(1568/64); 1568 = 24*64 + 32
#define ATTN_SMEM ((PBASE + 8 * 1088) * 4)   // 104448 B

__global__ void __launch_bounds__(256, 2) attn_mma()
{
    extern __shared__ __align__(16) uint32_t smw[];
    const uint32_t sbase = smem_u32(smw);

    const int b  = blockIdx.z;
    const int h  = blockIdx.y;
    const int q0 = blockIdx.x * 128;
    const int tid = threadIdx.x;
    const int w   = tid >> 5;
    const int lid = tid & 31;
    const int g   = lid >> 2;
    const int t   = lid & 3;
    const int tau = lid >> 3;
    const int lrw = lid & 7;

    const float* qb = g_q + (size_t)(b * HH + h) * SS * HDIM;
    const float* kb = g_k + (size_t)(b * HH + h) * SS * HDIM;
    const float* vb = g_v + (size_t)(b * HH + h) * SS * HDIM;

    const int cr  = tid >> 4;
    const int cc4 = tid & 15;

#define CPA_KV(kt_, buf_) do { \
    _Pragma("unroll") \
    for (int _i = 0; _i < 4; _i++) { \
        int _r = cr + _i * 16; \
        int _kr = (kt_) * 64 + _r; if (_kr >= SS) _kr = SS - 1; \
        uint32_t _d = sbase + ((buf_) * BUFW + _r * KVP + cc4 * 4) * 4; \
        cp_async16(_d,            kb + (size_t)_kr * HDIM + cc4 * 4); \
        cp_async16(_d + 4352 * 4, vb + (size_t)_kr * HDIM + cc4 * 4); \
    } \
} while (0)

#pragma unroll
    for (int i = 0; i < 8; i++) {
        int r = cr + i * 16;
        int qr = q0 + r; if (qr >= SS) qr = SS - 1;
        uint32_t d = sbase + (BUFW + r * KVP + cc4 * 4) * 4;
        cp_async16(d, qb + (size_t)qr * HDIM + cc4 * 4);
    }
    CP_COMMIT();
    CPA_KV(0, 0);
    CP_COMMIT();
    CP_WAIT(1);
    __syncthreads();

    uint32_t qf[8][4];
    {
        const uint32_t* Qb = smw + BUFW;
        const int r0 = (w * 16 + g) * KVP;
        const int r8 = r0 + 8 * KVP;
#pragma unroll
        for (int s = 0; s < 8; s++) {
            qf[s][0] = Qb[r0 + 8 * s + t];
            qf[s][1] = Qb[r8 + 8 * s + t];
            qf[s][2] = Qb[r0 + 8 * s + t + 4];
            qf[s][3] = Qb[r8 + 8 * s + t + 4];
        }
    }
    __syncthreads();
    CPA_KV(1, 1);
    CP_COMMIT();

    const uint32_t k_off =
        (uint32_t)(((8 * (tau >> 1) + lrw) * KVP + 4 * (tau & 1)) * 4);
    const uint32_t pw = sbase + (uint32_t)((PBASE + w * 1088) * 4);
    const uint32_t p_off =
        (uint32_t)(((lrw + 8 * (tau & 1)) * KVP + 4 * (tau >> 1)) * 4);
    uint32_t* Pw = smw + PBASE + w * 1088;

    float m0v = -1e30f, m1v = -1e30f, l0 = 0.f, l1 = 0.f;
    float ao[8][4];
#pragma unroll
    for (int nt = 0; nt < 8; nt++)
#pragma unroll
        for (int j = 0; j < 4; j++) ao[nt][j] = 0.f;

    for (int kt = 0; kt < NKT; kt++) {
        if (kt == NKT - 1) CP_WAIT(0); else CP_WAIT(1);
        __syncthreads();

        const uint32_t kbuf = (uint32_t)((kt & 1) * BUFW * 4);
        const uint32_t ka = sbase + kbuf + k_off;
        const uint32_t* Vb = smw + (kt & 1) * BUFW + 4352;

        float sf[8][4];
#pragma unroll
        for (int nt = 0; nt < 8; nt++)
#pragma unroll
            for (int j = 0; j < 4; j++) sf[nt][j] = 0.f;
#pragma unroll
        for (int s = 0; s < 8; s++) {
            uint32_t kf[16];
            LDMX4(kf[0],  kf[1],  kf[2],  kf[3],  ka + s * 32);
            LDMX4(kf[4],  kf[5],  kf[6],  kf[7],  ka + 4352 + s * 32);
            LDMX4(kf[8],  kf[9],  kf[10], kf[11], ka + 8704 + s * 32);
            LDMX4(kf[12], kf[13], kf[14], kf[15], ka + 13056 + s * 32);
#pragma unroll
            for (int nt = 0; nt < 8; nt++)
                MMA_TF32(sf[nt], qf[s], &kf[2 * nt]);
        }
        if (kt == NKT - 1) {
#pragma unroll
            for (int nt = 4; nt < 8; nt++) {
                sf[nt][0] = -1e30f; sf[nt][1] = -1e30f;
                sf[nt][2] = -1e30f; sf[nt][3] = -1e30f;
            }
        }

        float mx0 = -1e30f, mx1 = -1e30f;
#pragma unroll
        for (int nt = 0; nt < 8; nt++) {
            mx0 = fmaxf(mx0, fmaxf(sf[nt][0], sf[nt][1]));
            mx1 = fmaxf(mx1, fmaxf(sf[nt][2], sf[nt][3]));
        }
        mx0 = fmaxf(mx0, __shfl_xor_sync(0xffffffffu, mx0, 1));
        mx0 = fmaxf(mx0, __shfl_xor_sync(0xffffffffu, mx0, 2));
        mx1 = fmaxf(mx1, __shfl_xor_sync(0xffffffffu, mx1, 1));
        mx1 = fmaxf(mx1, __shfl_xor_sync(0xffffffffu, mx1, 2));
        const float mn0 = fmaxf(m0v, mx0);
        const float mn1 = fmaxf(m1v, mx1);
        const float a0 = __expf(m0v - mn0);
        const float a1 = __expf(m1v - mn1);
        m0v = mn0; m1v = mn1;

        float s0 = 0.f, s1 = 0.f;
#pragma unroll
        for (int nt = 0; nt < 8; nt++) {
            float e0 = __expf(sf[nt][0] - mn0);
            float e1 = __expf(sf[nt][1] - mn0);
            float e2 = __expf(sf[nt][2] - mn1);
            float e3 = __expf(sf[nt][3] - mn1);
            s0 += e0 + e1; s1 += e2 + e3;
            *(uint2*)&Pw[g * KVP + 8 * nt + 2 * t] =
                make_uint2(f2tf(e0), f2tf(e1));
            *(uint2*)&Pw[(g + 8) * KVP + 8 * nt + 2 * t] =
                make_uint2(f2tf(e2), f2tf(e3));
        }
        s0 += __shfl_xor_sync(0xffffffffu, s0, 1);
        s0 += __shfl_xor_sync(0xffffffffu, s0, 2);
        s1 += __shfl_xor_sync(0xffffffffu, s1, 1);
        s1 += __shfl_xor_sync(0xffffffffu, s1, 2);
        l0 = l0 * a0 + s0;
        l1 = l1 * a1 + s1;
#pragma unroll
        for (int nt = 0; nt < 8; nt++) {
            ao[nt][0] *= a0; ao[nt][1] *= a0;
            ao[nt][2] *= a1; ao[nt][3] *= a1;
        }
        __syncwarp();

#pragma unroll
        for (int s = 0; s < 8; s++) {
            uint32_t af[4];
            LDMX4(af[0], af[1], af[2], af[3], pw + p_off + s * 32);
            const int rb0 = (8 * s + t) * KVP + g;
#pragma unroll
            for (int nt = 0; nt < 8; nt++) {
                uint32_t bf[2];
                bf[0] = Vb[rb0 + 8 * nt];
                bf[1] = Vb[rb0 + 8 * nt + 4 * KVP];
                MMA_TF32(ao[nt], af, bf);
            }
        }
        __syncthreads();
        if (kt + 2 < NKT) { CPA_KV(kt + 2, kt & 1); CP_COMMIT(); }
    }

    const float i0 = 1.f / l0;
    const float i1 = 1.f / l1;
    const int qg = q0 + w * 16 + g;
    if (qg < SS) {
        float* row = g_ctx + (size_t)(b * SS + qg) * DD + h * HDIM;
#pragma unroll
        for (int nt = 0; nt < 8; nt++) {
            uint2 r = make_uint2(f2tf(ao[nt][0] * i0), f2tf(ao[nt][1] * i0));
            *(uint2*)&row[nt * 8 + 2 * t] = r;
        }
    }
    if (qg + 8 < SS) {
        float* row = g_ctx + (size_t)(b * SS + qg + 8) * DD + h * HDIM;
#pragma unroll
        for (int nt = 0; nt < 8; nt++) {
            uint2 r = make_uint2(f2tf(ao[nt][2] * i1), f2tf(ao[nt][3] * i1));
            *(uint2*)&row[nt * 8 + 2 * t] = r;
        }
    }
}

// ============================================================================
extern "C" void kernel_launch(void* const* d_in, const int* in_sizes, int n_in,
                              void* d_out, int out_size)
{
    const float* x  = (const float*)d_in[0];
    const float* Wq = (const float*)d_in[1];
    const float* bq = (const float*)d_in[2];
    const float* Wk = (const float*)d_in[3];
    const float* bk = (const float*)d_in[4];
    const float* Wv = (const float*)d_in[5];
    const float* bv = (const float*)d_in[6];
    const float* Wp = (const float*)d_in[7];
    const float* bp = (const float*)d_in[8];
    float* out = (float*)d_out;

    cudaFuncSetAttribute(gemm_tf32, cudaFuncAttributeMaxDynamicSharedMemorySize,
                         GEMM_SMEM);
    cudaFuncSetAttribute(attn_mma, cudaFuncAttributeMaxDynamicSharedMemorySize,
                         ATTN_SMEM);

    float *xr, *wr;
    cudaGetSymbolAddress((void**)&xr, g_xr);
    cudaGetSymbolAddress((void**)&wr, g_wr);

    // pre-round operands to tf32 (2 launches)
    round_tf32<<<(MTOT * DD / 4 + 255) / 256, 256>>>(x, xr, MTOT * DD / 4);
    round_w4<<<dim3(DD * DD / 4 / 256, 4), 256>>>(Wq, Wk, Wv, Wp, wr);

    // fused QKV projection: one launch, 48x49 blocks
    gemm_tf32<<<dim3(48, MTOT / 128), 256, GEMM_SMEM>>>(bq, bk, bv, nullptr);

    dim3 ga((SS + 127) / 128, HH, BB);  // 13 x 16 x 4
    attn_mma<<<ga, 256, ATTN_SMEM>>>();

    // output projection (mode 3 via outp != nullptr; bias passed as b0p)
    gemm_tf32<<<dim3(16, MTOT / 128), 256, GEMM_SMEM>>>(bp, bp, bp, out);
}

// round 16
// speedup vs baseline: 2.5773x; 1.1204x over previous
#include <cuda_runtime.h>
#include <cstdint>

#define BB   4
#define SS   1568
#define DD   1024
#define HH   16
#define HDIM 64
#define MTOT (BB*SS)          // 6272

// -------- scratch (no allocation allowed; __device__ globals) --------
__device__ float g_q[BB*HH*SS*HDIM];   // tf32-rounded, 0.125-scaled Q
__device__ float g_k[BB*HH*SS*HDIM];   // tf32-rounded K
__device__ float g_v[BB*HH*SS*HDIM];   // tf32-rounded V
__device__ float g_ctx[MTOT*DD];       // tf32-rounded ctx
__device__ float g_xr[MTOT*DD];        // tf32-rounded hidden_states
__device__ float g_wr[4*DD*DD];        // tf32-rounded Wq|Wk|Wv|Wp

// ============================================================================
// tf32 / async helpers (sm_80-class PTX — compiles under compute_103)
// ============================================================================
__device__ __forceinline__ uint32_t f2tf(float f) {
    uint32_t u;
    asm("cvt.rna.tf32.f32 %0, %1;" : "=r"(u) : "f"(f));
    return u;
}
__device__ __forceinline__ uint32_t smem_u32(const void* p) {
    uint32_t a;
    asm("{ .reg .u64 t; cvta.to.shared.u64 t, %1; cvt.u32.u64 %0, t; }"
        : "=r"(a) : "l"(p));
    return a;
}
__device__ __forceinline__ void cp_async16(uint32_t dst, const void* src) {
    asm volatile("cp.async.cg.shared.global [%0], [%1], 16;"
                 :: "r"(dst), "l"(src) : "memory");
}
#define CP_COMMIT() asm volatile("cp.async.commit_group;" ::: "memory")
#define CP_WAIT(n)  asm volatile("cp.async.wait_group %0;" :: "n"(n) : "memory")

#define MMA_TF32(c, a, b) \
    asm volatile("mma.sync.aligned.m16n8k8.row.col.f32.tf32.tf32.f32 " \
        "{%0,%1,%2,%3}, {%4,%5,%6,%7}, {%8,%9}, {%0,%1,%2,%3};" \
        : "+f"((c)[0]), "+f"((c)[1]), "+f"((c)[2]), "+f"((c)[3]) \
        : "r"((a)[0]), "r"((a)[1]), "r"((a)[2]), "r"((a)[3]), \
          "r"((b)[0]), "r"((b)[1]))

// 4x (8 rows x 16B) tiles; lane l supplies row l&7 of matrix l>>3.
// As 32-bit words: lane 4r+c of each matrix receives (row r, word c).
#define LDMX4(r0, r1, r2, r3, addr) \
    asm volatile("ldmatrix.sync.aligned.m8n8.x4.shared.b16 {%0,%1,%2,%3}, [%4];" \
        : "=r"(r0), "=r"(r1), "=r"(r2), "=r"(r3) : "r"(addr))

// ============================================================================
// Pre-round fp32 -> tf32 bits
// ============================================================================
__global__ void __launch_bounds__(256) round_tf32(
    const float* __restrict__ src, float* __restrict__ dst, int n4)
{
    int i = blockIdx.x * blockDim.x + threadIdx.x;
    if (i < n4) {
        float4 v = *(const float4*)(src + 4 * (size_t)i);
        uint4 u = make_uint4(f2tf(v.x), f2tf(v.y), f2tf(v.z), f2tf(v.w));
        *(uint4*)(dst + 4 * (size_t)i) = u;
    }
}

__global__ void __launch_bounds__(256) round_w4(
    const float* __restrict__ w0, const float* __restrict__ w1,
    const float* __restrict__ w2, const float* __restrict__ w3,
    float* __restrict__ dst)
{
    const float* src = (blockIdx.y == 0) ? w0 : (blockIdx.y == 1) ? w1
                     : (blockIdx.y == 2) ? w2 : w3;
    int i = blockIdx.x * blockDim.x + threadIdx.x;   // < DD*DD/4
    float4 v = *(const float4*)(src + 4 * (size_t)i);
    uint4 u = make_uint4(f2tf(v.x), f2tf(v.y), f2tf(v.z), f2tf(v.w));
    *(uint4*)(dst + (size_t)blockIdx.y * DD * DD + 4 * (size_t)i) = u;
}

// ============================================================================
// tf32 tensor-core GEMM: BM=128, BN=128, BK=32, 3-stage cp.async, ldmatrix.
// C[m,n] = sum_k A[m,k]*W[n,k] + bias[n].
// Stage (bytes): A 128x32 @ +0 (16 KB), B 128x32 @ +16384 (16 KB).
// Layout: word_off = r*32 + 4*(c4 ^ (r&7))  (same xor swizzle as R9-R14).
// 8 warps: wm=wid>>1 (M 32-slab), wn=wid&1 (N 64-slab); acc[2][8][4].
//
// Fused QKV (outp==nullptr): grid (24, 49); mode = bx>>3, n0 = (bx&7)*128.
// Out-proj  (outp!=nullptr): grid (8, 49); mode 3, A = g_ctx, raw fp32 out.
// ============================================================================
#define NCHUNK 32    // 1024 / 32
#define GSTB   32768 // bytes per stage
#define GEMM_SMEM (3 * GSTB)   // 98304 B

__global__ void __launch_bounds__(256, 2) gemm_tf32(
    const float* __restrict__ b0p, const float* __restrict__ b1p,
    const float* __restrict__ b2p, float* __restrict__ outp)
{
    extern __shared__ __align__(16) uint32_t smw[];
    const uint32_t sbase = smem_u32(smw);

    const int mode = outp ? 3 : ((int)blockIdx.x >> 3);
    const int n0   = (outp ? (int)blockIdx.x : ((int)blockIdx.x & 7)) * 128;
    const float* A = (mode == 3) ? g_ctx : g_xr;
    const float* bias = (mode == 0) ? b0p : (mode == 1) ? b1p
                      : (mode == 2) ? b2p : b0p;   // mode 3 passes bp as b0p
    const float* Wbase = g_wr + (size_t)mode * DD * DD;

    const int tid = threadIdx.x;
    const int wid = tid >> 5;
    const int lid = tid & 31;
    const int wm  = wid >> 1;          // 0..3  -> m slab wm*32
    const int wn  = wid & 1;           // 0..1  -> n slab wn*64
    const int g   = lid >> 2;
    const int t   = lid & 3;

    const int m0 = blockIdx.y * 128;

    const float* aP = A + (size_t)m0 * DD;
    const float* wP = Wbase + (size_t)n0 * DD;

    float acc[2][8][4];
#pragma unroll
    for (int mt = 0; mt < 2; mt++)
#pragma unroll
        for (int nt = 0; nt < 8; nt++)
#pragma unroll
            for (int j = 0; j < 4; j++) acc[mt][nt][j] = 0.f;

    // cp.async: A and B each 1024 16B-units per chunk (4 per thread each)
#define GCPA(kc, stg) do { \
    uint32_t _sb = sbase + (uint32_t)(stg) * GSTB; \
    _Pragma("unroll") \
    for (int _i = 0; _i < 4; _i++) { \
        int _idx = tid + _i * 256; \
        int _r = _idx >> 3, _c4 = _idx & 7; \
        uint32_t _o = (uint32_t)(_r * 128 + 16 * (_c4 ^ (_r & 7))); \
        cp_async16(_sb + _o, \
                   aP + (size_t)_r * DD + (kc) * 32 + _c4 * 4); \
        cp_async16(_sb + 16384 + _o, \
                   wP + (size_t)_r * DD + (kc) * 32 + _c4 * 4); \
    } \
    CP_COMMIT(); \
} while (0)

    GCPA(0, 0);
    GCPA(1, 1);

    // ldmatrix per-lane bases (byte offsets within stage)
    // A m16k8 frag (rows wm*32+mt*16.., k 8s..): matrices ordered
    //   (rowhalf0,j0),(rowhalf1,j0),(rowhalf0,j1),(rowhalf1,j1) -> a0..a3
    const int x7  = lid & 7;                       // xor key (= r&7 for all)
    const int rA0 = wm * 32 + ((lid >> 3) & 1) * 8 + x7;
    // B n8k8 tiles: per instr 4 matrices (nt,j0),(nt,j1),(nt+1,j0),(nt+1,j1)
    const int rB0 = wn * 64 + 8 * (lid >> 4) + x7;
    const int caH = lid >> 4;                      // A c4 high part
    const int cbH = (lid >> 3) & 1;                // B c4 high part

    int stg = 2;   // next stage to fill
    for (int c = 0; c < NCHUNK; c++) {
        if (c < NCHUNK - 1) CP_WAIT(1); else CP_WAIT(0);
        __syncthreads();
        if (c + 2 < NCHUNK) {
            GCPA(c + 2, stg);
            stg = (stg == 2) ? 0 : stg + 1;
        }

        const uint32_t sA = sbase + (uint32_t)(c % 3) * GSTB;
        const uint32_t sB = sA + 16384;
#pragma unroll
        for (int s = 0; s < 4; s++) {
            const int ca = 2 * s + caH;
            const int cb = 2 * s + cbH;
            uint32_t af[2][4], bf[8][2];
#pragma unroll
            for (int mt = 0; mt < 2; mt++) {
                uint32_t addr = sA + (uint32_t)((rA0 + 16 * mt) * 128
                                                + 16 * (ca ^ x7));
                LDMX4(af[mt][0], af[mt][1], af[mt][2], af[mt][3], addr);
            }
#pragma unroll
            for (int p = 0; p < 4; p++) {
                uint32_t addr = sB + (uint32_t)((rB0 + 16 * p) * 128
                                                + 16 * (cb ^ x7));
                LDMX4(bf[2 * p][0], bf[2 * p][1],
                      bf[2 * p + 1][0], bf[2 * p + 1][1], addr);
            }
#pragma unroll
            for (int mt = 0; mt < 2; mt++)
#pragma unroll
                for (int nt = 0; nt < 8; nt++)
                    MMA_TF32(acc[mt][nt], af[mt], bf[nt]);
        }
    }

    // epilogue
    float* qkv = (mode == 0) ? g_q : (mode == 1) ? g_k : g_v;
    const float sc = (mode == 0) ? 0.125f : 1.0f;
#pragma unroll
    for (int mt = 0; mt < 2; mt++) {
#pragma unroll
        for (int half = 0; half < 2; half++) {
            int row = m0 + wm * 32 + mt * 16 + g + half * 8;
            int b = row / SS, sx = row % SS;
#pragma unroll
            for (int nt = 0; nt < 8; nt++) {
                int n = n0 + wn * 64 + nt * 8 + 2 * t;
                float2 bv = *(const float2*)&bias[n];
                float2 r;
                r.x = acc[mt][nt][half * 2 + 0] + bv.x;
                r.y = acc[mt][nt][half * 2 + 1] + bv.y;
                if (mode == 3) {
                    *(float2*)&outp[(size_t)row * DD + n] = r;
                } else {
                    int h = n >> 6;
                    uint2 u = make_uint2(f2tf(r.x * sc), f2tf(r.y * sc));
                    *(uint2*)&qkv[(size_t)((b * HH + h) * SS + sx) * HDIM
                                  + (n & 63)] = u;
                }
            }
        }
    }
}

// ============================================================================
// Tensor-core flash attention (byte-identical math to R13/R14).
// ============================================================================
#define KVP 68              // smem pitch (words)
#define BUFW 8704           // words per KV buffer (2 * 64 * 68)
#define PBASE 17408         // word offset of P slabs
#define NKT 25              // ceil(1568/64); 1568 = 24*64 + 32
#define ATTN_SMEM ((PBASE + 8 * 1088) * 4)   // 104448 B

__global__ void __launch_bounds__(256, 2) attn_mma()
{
    extern __shared__ __align__(16) uint32_t smw[];
    const uint32_t sbase = smem_u32(smw);

    const int b  = blockIdx.z;
    const int h  = blockIdx.y;
    const int q0 = blockIdx.x * 128;
    const int tid = threadIdx.x;
    const int w   = tid >> 5;
    const int lid = tid & 31;
    const int g   = lid >> 2;
    const int t   = lid & 3;
    const int tau = lid >> 3;
    const int lrw = lid & 7;

    const float* qb = g_q + (size_t)(b * HH + h) * SS * HDIM;
    const float* kb = g_k + (size_t)(b * HH + h) * SS * HDIM;
    const float* vb = g_v + (size_t)(b * HH + h) * SS * HDIM;

    const int cr  = tid >> 4;
    const int cc4 = tid & 15;

#define CPA_KV(kt_, buf_) do { \
    _Pragma("unroll") \
    for (int _i = 0; _i < 4; _i++) { \
        int _r = cr + _i * 16; \
        int _kr = (kt_) * 64 + _r; if (_kr >= SS) _kr = SS - 1; \
        uint32_t _d = sbase + ((buf_) * BUFW + _r * KVP + cc4 * 4) * 4; \
        cp_async16(_d,            kb + (size_t)_kr * HDIM + cc4 * 4); \
        cp_async16(_d + 4352 * 4, vb + (size_t)_kr * HDIM + cc4 * 4); \
    } \
} while (0)

#pragma unroll
    for (int i = 0; i < 8; i++) {
        int r = cr + i * 16;
        int qr = q0 + r; if (qr >= SS) qr = SS - 1;
        uint32_t d = sbase + (BUFW + r * KVP + cc4 * 4) * 4;
        cp_async16(d, qb + (size_t)qr * HDIM + cc4 * 4);
    }
    CP_COMMIT();
    CPA_KV(0, 0);
    CP_COMMIT();
    CP_WAIT(1);
    __syncthreads();

    uint32_t qf[8][4];
    {
        const uint32_t* Qb = smw + BUFW;
        const int r0 = (w * 16 + g) * KVP;
        const int r8 = r0 + 8 * KVP;
#pragma unroll
        for (int s = 0; s < 8; s++) {
            qf[s][0] = Qb[r0 + 8 * s + t];
            qf[s][1] = Qb[r8 + 8 * s + t];
            qf[s][2] = Qb[r0 + 8 * s + t + 4];
            qf[s][3] = Qb[r8 + 8 * s + t + 4];
        }
    }
    __syncthreads();
    CPA_KV(1, 1);
    CP_COMMIT();

    const uint32_t k_off =
        (uint32_t)(((8 * (tau >> 1) + lrw) * KVP + 4 * (tau & 1)) * 4);
    const uint32_t pw = sbase + (uint32_t)((PBASE + w * 1088) * 4);
    const uint32_t p_off =
        (uint32_t)(((lrw + 8 * (tau & 1)) * KVP + 4 * (tau >> 1)) * 4);
    uint32_t* Pw = smw + PBASE + w * 1088;

    float m0v = -1e30f, m1v = -1e30f, l0 = 0.f, l1 = 0.f;
    float ao[8][4];
#pragma unroll
    for (int nt = 0; nt < 8; nt++)
#pragma unroll
        for (int j = 0; j < 4; j++) ao[nt][j] = 0.f;

    for (int kt = 0; kt < NKT; kt++) {
        if (kt == NKT - 1) CP_WAIT(0); else CP_WAIT(1);
        __syncthreads();

        const uint32_t kbuf = (uint32_t)((kt & 1) * BUFW * 4);
        const uint32_t ka = sbase + kbuf + k_off;
        const uint32_t* Vb = smw + (kt & 1) * BUFW + 4352;

        float sf[8][4];
#pragma unroll
        for (int nt = 0; nt < 8; nt++)
#pragma unroll
            for (int j = 0; j < 4; j++) sf[nt][j] = 0.f;
#pragma unroll
        for (int s = 0; s < 8; s++) {
            uint32_t kf[16];
            LDMX4(kf[0],  kf[1],  kf[2],  kf[3],  ka + s * 32);
            LDMX4(kf[4],  kf[5],  kf[6],  kf[7],  ka + 4352 + s * 32);
            LDMX4(kf[8],  kf[9],  kf[10], kf[11], ka + 8704 + s * 32);
            LDMX4(kf[12], kf[13], kf[14], kf[15], ka + 13056 + s * 32);
#pragma unroll
            for (int nt = 0; nt < 8; nt++)
                MMA_TF32(sf[nt], qf[s], &kf[2 * nt]);
        }
        if (kt == NKT - 1) {
#pragma unroll
            for (int nt = 4; nt < 8; nt++) {
                sf[nt][0] = -1e30f; sf[nt][1] = -1e30f;
                sf[nt][2] = -1e30f; sf[nt][3] = -1e30f;
            }
        }

        float mx0 = -1e30f, mx1 = -1e30f;
#pragma unroll
        for (int nt = 0; nt < 8; nt++) {
            mx0 = fmaxf(mx0, fmaxf(sf[nt][0], sf[nt][1]));
            mx1 = fmaxf(mx1, fmaxf(sf[nt][2], sf[nt][3]));
        }
        mx0 = fmaxf(mx0, __shfl_xor_sync(0xffffffffu, mx0, 1));
        mx0 = fmaxf(mx0, __shfl_xor_sync(0xffffffffu, mx0, 2));
        mx1 = fmaxf(mx1, __shfl_xor_sync(0xffffffffu, mx1, 1));
        mx1 = fmaxf(mx1, __shfl_xor_sync(0xffffffffu, mx1, 2));
        const float mn0 = fmaxf(m0v, mx0);
        const float mn1 = fmaxf(m1v, mx1);
        const float a0 = __expf(m0v - mn0);
        const float a1 = __expf(m1v - mn1);
        m0v = mn0; m1v = mn1;

        float s0 = 0.f, s1 = 0.f;
#pragma unroll
        for (int nt = 0; nt < 8; nt++) {
            float e0 = __expf(sf[nt][0] - mn0);
            float e1 = __expf(sf[nt][1] - mn0);
            float e2 = __expf(sf[nt][2] - mn1);
            float e3 = __expf(sf[nt][3] - mn1);
            s0 += e0 + e1; s1 += e2 + e3;
            *(uint2*)&Pw[g * KVP + 8 * nt + 2 * t] =
                make_uint2(f2tf(e0), f2tf(e1));
            *(uint2*)&Pw[(g + 8) * KVP + 8 * nt + 2 * t] =
                make_uint2(f2tf(e2), f2tf(e3));
        }
        s0 += __shfl_xor_sync(0xffffffffu, s0, 1);
        s0 += __shfl_xor_sync(0xffffffffu, s0, 2);
        s1 += __shfl_xor_sync(0xffffffffu, s1, 1);
        s1 += __shfl_xor_sync(0xffffffffu, s1, 2);
        l0 = l0 * a0 + s0;
        l1 = l1 * a1 + s1;
#pragma unroll
        for (int nt = 0; nt < 8; nt++) {
            ao[nt][0] *= a0; ao[nt][1] *= a0;
            ao[nt][2] *= a1; ao[nt][3] *= a1;
        }
        __syncwarp();

#pragma unroll
        for (int s = 0; s < 8; s++) {
            uint32_t af[4];
            LDMX4(af[0], af[1], af[2], af[3], pw + p_off + s * 32);
            const int rb0 = (8 * s + t) * KVP + g;
#pragma unroll
            for (int nt = 0; nt < 8; nt++) {
                uint32_t bf[2];
                bf[0] = Vb[rb0 + 8 * nt];
                bf[1] = Vb[rb0 + 8 * nt + 4 * KVP];
                MMA_TF32(ao[nt], af, bf);
            }
        }
        __syncthreads();
        if (kt + 2 < NKT) { CPA_KV(kt + 2, kt & 1); CP_COMMIT(); }
    }

    const float i0 = 1.f / l0;
    const float i1 = 1.f / l1;
    const int qg = q0 + w * 16 + g;
    if (qg < SS) {
        float* row = g_ctx + (size_t)(b * SS + qg) * DD + h * HDIM;
#pragma unroll
        for (int nt = 0; nt < 8; nt++) {
            uint2 r = make_uint2(f2tf(ao[nt][0] * i0), f2tf(ao[nt][1] * i0));
            *(uint2*)&row[nt * 8 + 2 * t] = r;
        }
    }
    if (qg + 8 < SS) {
        float* row = g_ctx + (size_t)(b * SS + qg + 8) * DD + h * HDIM;
#pragma unroll
        for (int nt = 0; nt < 8; nt++) {
            uint2 r = make_uint2(f2tf(ao[nt][2] * i1), f2tf(ao[nt][3] * i1));
            *(uint2*)&row[nt * 8 + 2 * t] = r;
        }
    }
}

// ============================================================================
extern "C" void kernel_launch(void* const* d_in, const int* in_sizes, int n_in,
                              void* d_out, int out_size)
{
    const float* x  = (const float*)d_in[0];
    const float* Wq = (const float*)d_in[1];
    const float* bq = (const float*)d_in[2];
    const float* Wk = (const float*)d_in[3];
    const float* bk = (const float*)d_in[4];
    const float* Wv = (const float*)d_in[5];
    const float* bv = (const float*)d_in[6];
    const float* Wp = (const float*)d_in[7];
    const float* bp = (const float*)d_in[8];
    float* out = (float*)d_out;

    cudaFuncSetAttribute(gemm_tf32, cudaFuncAttributeMaxDynamicSharedMemorySize,
                         GEMM_SMEM);
    cudaFuncSetAttribute(attn_mma, cudaFuncAttributeMaxDynamicSharedMemorySize,
                         ATTN_SMEM);

    float *xr, *wr;
    cudaGetSymbolAddress((void**)&xr, g_xr);
    cudaGetSymbolAddress((void**)&wr, g_wr);

    // pre-round operands to tf32 (2 launches)
    round_tf32<<<(MTOT * DD / 4 + 255) / 256, 256>>>(x, xr, MTOT * DD / 4);
    round_w4<<<dim3(DD * DD / 4 / 256, 4), 256>>>(Wq, Wk, Wv, Wp, wr);

    // fused QKV projection: grid (24, 49), BN=128
    gemm_tf32<<<dim3(24, MTOT / 128), 256, GEMM_SMEM>>>(bq, bk, bv, nullptr);

    dim3 ga((SS + 127) / 128, HH, BB);  // 13 x 16 x 4
    attn_mma<<<ga, 256, ATTN_SMEM>>>();

    // output projection: grid (8, 49)
    gemm_tf32<<<dim3(8, MTOT / 128), 256, GEMM_SMEM>>>(bp, bp, bp, out);
}

// round 17
// speedup vs baseline: 2.6427x; 1.0254x over previous
#include <cuda_runtime.h>
#include <cstdint>

#define BB   4
#define SS   1568
#define DD   1024
#define HH   16
#define HDIM 64
#define MTOT (BB*SS)          // 6272

// -------- scratch (no allocation allowed; __device__ globals) --------
__device__ float g_q[BB*HH*SS*HDIM];   // tf32-rounded, 0.125-scaled Q
__device__ float g_k[BB*HH*SS*HDIM];   // tf32-rounded K
__device__ float g_v[BB*HH*SS*HDIM];   // tf32-rounded V
__device__ float g_ctx[MTOT*DD];       // tf32-rounded ctx
__device__ float g_xr[MTOT*DD];        // tf32-rounded hidden_states
__device__ float g_wr[4*DD*DD];        // tf32-rounded Wq|Wk|Wv|Wp

// ============================================================================
// tf32 / async helpers (sm_80-class PTX — compiles under compute_103)
// ============================================================================
__device__ __forceinline__ uint32_t f2tf(float f) {
    uint32_t u;
    asm("cvt.rna.tf32.f32 %0, %1;" : "=r"(u) : "f"(f));
    return u;
}
__device__ __forceinline__ uint32_t smem_u32(const void* p) {
    uint32_t a;
    asm("{ .reg .u64 t; cvta.to.shared.u64 t, %1; cvt.u32.u64 %0, t; }"
        : "=r"(a) : "l"(p));
    return a;
}
__device__ __forceinline__ void cp_async16(uint32_t dst, const void* src) {
    asm volatile("cp.async.cg.shared.global [%0], [%1], 16;"
                 :: "r"(dst), "l"(src) : "memory");
}
#define CP_COMMIT() asm volatile("cp.async.commit_group;" ::: "memory")
#define CP_WAIT(n)  asm volatile("cp.async.wait_group %0;" :: "n"(n) : "memory")

#define MMA_TF32(c, a, b) \
    asm volatile("mma.sync.aligned.m16n8k8.row.col.f32.tf32.tf32.f32 " \
        "{%0,%1,%2,%3}, {%4,%5,%6,%7}, {%8,%9}, {%0,%1,%2,%3};" \
        : "+f"((c)[0]), "+f"((c)[1]), "+f"((c)[2]), "+f"((c)[3]) \
        : "r"((a)[0]), "r"((a)[1]), "r"((a)[2]), "r"((a)[3]), \
          "r"((b)[0]), "r"((b)[1]))

// 4x (8 rows x 16B) tiles; lane l supplies row l&7 of matrix l>>3.
// As 32-bit words: lane 4r+c of each matrix receives (row r, word c).
#define LDMX4(r0, r1, r2, r3, addr) \
    asm volatile("ldmatrix.sync.aligned.m8n8.x4.shared.b16 {%0,%1,%2,%3}, [%4];" \
        : "=r"(r0), "=r"(r1), "=r"(r2), "=r"(r3) : "r"(addr))

// ============================================================================
// Pre-round fp32 -> tf32 bits: x (6272 blocks) + 4 W (4096 blocks), one launch
// ============================================================================
__global__ void __launch_bounds__(256) round_all(
    const float* __restrict__ x,
    const float* __restrict__ w0, const float* __restrict__ w1,
    const float* __restrict__ w2, const float* __restrict__ w3,
    float* __restrict__ xdst, float* __restrict__ wdst)
{
    const int bid = blockIdx.x;
    const float* src;
    float* dst;
    int i;
    if (bid < MTOT * DD / 4 / 256) {           // 6272 x-blocks
        i = bid * 256 + threadIdx.x;
        src = x; dst = xdst;
    } else {
        int wb = bid - MTOT * DD / 4 / 256;    // 0..4095
        int wsel = wb >> 10;
        src = (wsel == 0) ? w0 : (wsel == 1) ? w1 : (wsel == 2) ? w2 : w3;
        dst = wdst + (size_t)wsel * DD * DD;
        i = (wb & 1023) * 256 + threadIdx.x;
    }
    float4 v = *(const float4*)(src + 4 * (size_t)i);
    uint4 u = make_uint4(f2tf(v.x), f2tf(v.y), f2tf(v.z), f2tf(v.w));
    *(uint4*)(dst + 4 * (size_t)i) = u;
}

// ============================================================================
// tf32 tensor-core GEMM (byte-identical to R15).
// BM=128, BN=128, BK=32, 3-stage cp.async, ldmatrix fragments.
// ============================================================================
#define NCHUNK 32    // 1024 / 32
#define GSTB   32768 // bytes per stage
#define GEMM_SMEM (3 * GSTB)   // 98304 B

__global__ void __launch_bounds__(256, 2) gemm_tf32(
    const float* __restrict__ b0p, const float* __restrict__ b1p,
    const float* __restrict__ b2p, float* __restrict__ outp)
{
    extern __shared__ __align__(16) uint32_t smw[];
    const uint32_t sbase = smem_u32(smw);

    const int mode = outp ? 3 : ((int)blockIdx.x >> 3);
    const int n0   = (outp ? (int)blockIdx.x : ((int)blockIdx.x & 7)) * 128;
    const float* A = (mode == 3) ? g_ctx : g_xr;
    const float* bias = (mode == 0) ? b0p : (mode == 1) ? b1p
                      : (mode == 2) ? b2p : b0p;
    const float* Wbase = g_wr + (size_t)mode * DD * DD;

    const int tid = threadIdx.x;
    const int wid = tid >> 5;
    const int lid = tid & 31;
    const int wm  = wid >> 1;
    const int wn  = wid & 1;
    const int g   = lid >> 2;
    const int t   = lid & 3;

    const int m0 = blockIdx.y * 128;

    const float* aP = A + (size_t)m0 * DD;
    const float* wP = Wbase + (size_t)n0 * DD;

    float acc[2][8][4];
#pragma unroll
    for (int mt = 0; mt < 2; mt++)
#pragma unroll
        for (int nt = 0; nt < 8; nt++)
#pragma unroll
            for (int j = 0; j < 4; j++) acc[mt][nt][j] = 0.f;

#define GCPA(kc, stg) do { \
    uint32_t _sb = sbase + (uint32_t)(stg) * GSTB; \
    _Pragma("unroll") \
    for (int _i = 0; _i < 4; _i++) { \
        int _idx = tid + _i * 256; \
        int _r = _idx >> 3, _c4 = _idx & 7; \
        uint32_t _o = (uint32_t)(_r * 128 + 16 * (_c4 ^ (_r & 7))); \
        cp_async16(_sb + _o, \
                   aP + (size_t)_r * DD + (kc) * 32 + _c4 * 4); \
        cp_async16(_sb + 16384 + _o, \
                   wP + (size_t)_r * DD + (kc) * 32 + _c4 * 4); \
    } \
    CP_COMMIT(); \
} while (0)

    GCPA(0, 0);
    GCPA(1, 1);

    const int x7  = lid & 7;
    const int rA0 = wm * 32 + ((lid >> 3) & 1) * 8 + x7;
    const int rB0 = wn * 64 + 8 * (lid >> 4) + x7;
    const int caH = lid >> 4;
    const int cbH = (lid >> 3) & 1;

    int stg = 2;
    for (int c = 0; c < NCHUNK; c++) {
        if (c < NCHUNK - 1) CP_WAIT(1); else CP_WAIT(0);
        __syncthreads();
        if (c + 2 < NCHUNK) {
            GCPA(c + 2, stg);
            stg = (stg == 2) ? 0 : stg + 1;
        }

        const uint32_t sA = sbase + (uint32_t)(c % 3) * GSTB;
        const uint32_t sB = sA + 16384;
#pragma unroll
        for (int s = 0; s < 4; s++) {
            const int ca = 2 * s + caH;
            const int cb = 2 * s + cbH;
            uint32_t af[2][4], bf[8][2];
#pragma unroll
            for (int mt = 0; mt < 2; mt++) {
                uint32_t addr = sA + (uint32_t)((rA0 + 16 * mt) * 128
                                                + 16 * (ca ^ x7));
                LDMX4(af[mt][0], af[mt][1], af[mt][2], af[mt][3], addr);
            }
#pragma unroll
            for (int p = 0; p < 4; p++) {
                uint32_t addr = sB + (uint32_t)((rB0 + 16 * p) * 128
                                                + 16 * (cb ^ x7));
                LDMX4(bf[2 * p][0], bf[2 * p][1],
                      bf[2 * p + 1][0], bf[2 * p + 1][1], addr);
            }
#pragma unroll
            for (int mt = 0; mt < 2; mt++)
#pragma unroll
                for (int nt = 0; nt < 8; nt++)
                    MMA_TF32(acc[mt][nt], af[mt], bf[nt]);
        }
    }

    float* qkv = (mode == 0) ? g_q : (mode == 1) ? g_k : g_v;
    const float sc = (mode == 0) ? 0.125f : 1.0f;
#pragma unroll
    for (int mt = 0; mt < 2; mt++) {
#pragma unroll
        for (int half = 0; half < 2; half++) {
            int row = m0 + wm * 32 + mt * 16 + g + half * 8;
            int b = row / SS, sx = row % SS;
#pragma unroll
            for (int nt = 0; nt < 8; nt++) {
                int n = n0 + wn * 64 + nt * 8 + 2 * t;
                float2 bv = *(const float2*)&bias[n];
                float2 r;
                r.x = acc[mt][nt][half * 2 + 0] + bv.x;
                r.y = acc[mt][nt][half * 2 + 1] + bv.y;
                if (mode == 3) {
                    *(float2*)&outp[(size_t)row * DD + n] = r;
                } else {
                    int h = n >> 6;
                    uint2 u = make_uint2(f2tf(r.x * sc), f2tf(r.y * sc));
                    *(uint2*)&qkv[(size_t)((b * HH + h) * SS + sx) * HDIM
                                  + (n & 63)] = u;
                }
            }
        }
    }
}

// ============================================================================
// Tensor-core flash attention: exp/store/PV pipelined per key-group.
// ============================================================================
#define KVP 68              // smem pitch (words)
#define BUFW 8704           // words per KV buffer (2 * 64 * 68)
#define PBASE 17408         // word offset of P slabs
#define NKT 25              // ceil(1568/64); 1568 = 24*64 + 32
#define ATTN_SMEM ((PBASE + 8 * 1088) * 4)   // 104448 B

__global__ void __launch_bounds__(256, 2) attn_mma()
{
    extern __shared__ __align__(16) uint32_t smw[];
    const uint32_t sbase = smem_u32(smw);

    const int b  = blockIdx.z;
    const int h  = blockIdx.y;
    const int q0 = blockIdx.x * 128;
    const int tid = threadIdx.x;
    const int w   = tid >> 5;
    const int lid = tid & 31;
    const int g   = lid >> 2;
    const int t   = lid & 3;
    const int tau = lid >> 3;
    const int lrw = lid & 7;

    const float* qb = g_q + (size_t)(b * HH + h) * SS * HDIM;
    const float* kb = g_k + (size_t)(b * HH + h) * SS * HDIM;
    const float* vb = g_v + (size_t)(b * HH + h) * SS * HDIM;

    const int cr  = tid >> 4;
    const int cc4 = tid & 15;

#define CPA_KV(kt_, buf_) do { \
    _Pragma("unroll") \
    for (int _i = 0; _i < 4; _i++) { \
        int _r = cr + _i * 16; \
        int _kr = (kt_) * 64 + _r; if (_kr >= SS) _kr = SS - 1; \
        uint32_t _d = sbase + ((buf_) * BUFW + _r * KVP + cc4 * 4) * 4; \
        cp_async16(_d,            kb + (size_t)_kr * HDIM + cc4 * 4); \
        cp_async16(_d + 4352 * 4, vb + (size_t)_kr * HDIM + cc4 * 4); \
    } \
} while (0)

#pragma unroll
    for (int i = 0; i < 8; i++) {
        int r = cr + i * 16;
        int qr = q0 + r; if (qr >= SS) qr = SS - 1;
        uint32_t d = sbase + (BUFW + r * KVP + cc4 * 4) * 4;
        cp_async16(d, qb + (size_t)qr * HDIM + cc4 * 4);
    }
    CP_COMMIT();
    CPA_KV(0, 0);
    CP_COMMIT();
    CP_WAIT(1);
    __syncthreads();

    uint32_t qf[8][4];
    {
        const uint32_t* Qb = smw + BUFW;
        const int r0 = (w * 16 + g) * KVP;
        const int r8 = r0 + 8 * KVP;
#pragma unroll
        for (int s = 0; s < 8; s++) {
            qf[s][0] = Qb[r0 + 8 * s + t];
            qf[s][1] = Qb[r8 + 8 * s + t];
            qf[s][2] = Qb[r0 + 8 * s + t + 4];
            qf[s][3] = Qb[r8 + 8 * s + t + 4];
        }
    }
    __syncthreads();
    CPA_KV(1, 1);
    CP_COMMIT();

    const uint32_t k_off =
        (uint32_t)(((8 * (tau >> 1) + lrw) * KVP + 4 * (tau & 1)) * 4);
    const uint32_t pw = sbase + (uint32_t)((PBASE + w * 1088) * 4);
    const uint32_t p_off =
        (uint32_t)(((lrw + 8 * (tau & 1)) * KVP + 4 * (tau >> 1)) * 4);
    uint32_t* Pw = smw + PBASE + w * 1088;

    float m0v = -1e30f, m1v = -1e30f, l0 = 0.f, l1 = 0.f;
    float ao[8][4];
#pragma unroll
    for (int nt = 0; nt < 8; nt++)
#pragma unroll
        for (int j = 0; j < 4; j++) ao[nt][j] = 0.f;

    for (int kt = 0; kt < NKT; kt++) {
        if (kt == NKT - 1) CP_WAIT(0); else CP_WAIT(1);
        __syncthreads();

        const uint32_t kbuf = (uint32_t)((kt & 1) * BUFW * 4);
        const uint32_t ka = sbase + kbuf + k_off;
        const uint32_t* Vb = smw + (kt & 1) * BUFW + 4352;

        // ---- S = Q K^T ----
        float sf[8][4];
#pragma unroll
        for (int nt = 0; nt < 8; nt++)
#pragma unroll
            for (int j = 0; j < 4; j++) sf[nt][j] = 0.f;
#pragma unroll
        for (int s = 0; s < 8; s++) {
            uint32_t kf[16];
            LDMX4(kf[0],  kf[1],  kf[2],  kf[3],  ka + s * 32);
            LDMX4(kf[4],  kf[5],  kf[6],  kf[7],  ka + 4352 + s * 32);
            LDMX4(kf[8],  kf[9],  kf[10], kf[11], ka + 8704 + s * 32);
            LDMX4(kf[12], kf[13], kf[14], kf[15], ka + 13056 + s * 32);
#pragma unroll
            for (int nt = 0; nt < 8; nt++)
                MMA_TF32(sf[nt], qf[s], &kf[2 * nt]);
        }
        if (kt == NKT - 1) {          // 1568 = 24*64+32: n-tiles 4..7 invalid
#pragma unroll
            for (int nt = 4; nt < 8; nt++) {
                sf[nt][0] = -1e30f; sf[nt][1] = -1e30f;
                sf[nt][2] = -1e30f; sf[nt][3] = -1e30f;
            }
        }

        // ---- max reduce (tree form), rescale ----
        float tm0[4], tm1[4];
#pragma unroll
        for (int i = 0; i < 4; i++) {
            tm0[i] = fmaxf(fmaxf(sf[2 * i][0], sf[2 * i][1]),
                           fmaxf(sf[2 * i + 1][0], sf[2 * i + 1][1]));
            tm1[i] = fmaxf(fmaxf(sf[2 * i][2], sf[2 * i][3]),
                           fmaxf(sf[2 * i + 1][2], sf[2 * i + 1][3]));
        }
        float mx0 = fmaxf(fmaxf(tm0[0], tm0[1]), fmaxf(tm0[2], tm0[3]));
        float mx1 = fmaxf(fmaxf(tm1[0], tm1[1]), fmaxf(tm1[2], tm1[3]));
        mx0 = fmaxf(mx0, __shfl_xor_sync(0xffffffffu, mx0, 1));
        mx0 = fmaxf(mx0, __shfl_xor_sync(0xffffffffu, mx0, 2));
        mx1 = fmaxf(mx1, __shfl_xor_sync(0xffffffffu, mx1, 1));
        mx1 = fmaxf(mx1, __shfl_xor_sync(0xffffffffu, mx1, 2));
        const float mn0 = fmaxf(m0v, mx0);
        const float mn1 = fmaxf(m1v, mx1);
        const float a0 = __expf(m0v - mn0);
        const float a1 = __expf(m1v - mn1);
        m0v = mn0; m1v = mn1;
        l0 *= a0; l1 *= a1;
#pragma unroll
        for (int nt = 0; nt < 8; nt++) {
            ao[nt][0] *= a0; ao[nt][1] *= a0;
            ao[nt][2] *= a1; ao[nt][3] *= a1;
        }

        // ---- pipelined exp -> P store -> ldmatrix -> PV-MMA ----
        float s0 = 0.f, s1 = 0.f;
#define EXPSTORE(sx) do { \
        float _e0 = __expf(sf[sx][0] - mn0); \
        float _e1 = __expf(sf[sx][1] - mn0); \
        float _e2 = __expf(sf[sx][2] - mn1); \
        float _e3 = __expf(sf[sx][3] - mn1); \
        s0 += _e0 + _e1; s1 += _e2 + _e3; \
        *(uint2*)&Pw[g * KVP + 8 * (sx) + 2 * t] = \
            make_uint2(f2tf(_e0), f2tf(_e1)); \
        *(uint2*)&Pw[(g + 8) * KVP + 8 * (sx) + 2 * t] = \
            make_uint2(f2tf(_e2), f2tf(_e3)); \
} while (0)

        EXPSTORE(0);
        EXPSTORE(1);
        __syncwarp();
#pragma unroll
        for (int s = 0; s < 8; s++) {
            if (s < 6) EXPSTORE(s + 2);
            uint32_t af[4];
            LDMX4(af[0], af[1], af[2], af[3], pw + p_off + s * 32);
            const int rb0 = (8 * s + t) * KVP + g;
#pragma unroll
            for (int nt = 0; nt < 8; nt++) {
                uint32_t bf[2];
                bf[0] = Vb[rb0 + 8 * nt];
                bf[1] = Vb[rb0 + 8 * nt + 4 * KVP];
                MMA_TF32(ao[nt], af, bf);
            }
            if (s == 1 || s == 3 || s == 5) __syncwarp();
        }
#undef EXPSTORE
        s0 += __shfl_xor_sync(0xffffffffu, s0, 1);
        s0 += __shfl_xor_sync(0xffffffffu, s0, 2);
        s1 += __shfl_xor_sync(0xffffffffu, s1, 1);
        s1 += __shfl_xor_sync(0xffffffffu, s1, 2);
        l0 += s0; l1 += s1;

        __syncthreads();
        if (kt + 2 < NKT) { CPA_KV(kt + 2, kt & 1); CP_COMMIT(); }
    }

    const float i0 = 1.f / l0;
    const float i1 = 1.f / l1;
    const int qg = q0 + w * 16 + g;
    if (qg < SS) {
        float* row = g_ctx + (size_t)(b * SS + qg) * DD + h * HDIM;
#pragma unroll
        for (int nt = 0; nt < 8; nt++) {
            uint2 r = make_uint2(f2tf(ao[nt][0] * i0), f2tf(ao[nt][1] * i0));
            *(uint2*)&row[nt * 8 + 2 * t] = r;
        }
    }
    if (qg + 8 < SS) {
        float* row = g_ctx + (size_t)(b * SS + qg + 8) * DD + h * HDIM;
#pragma unroll
        for (int nt = 0; nt < 8; nt++) {
            uint2 r = make_uint2(f2tf(ao[nt][2] * i1), f2tf(ao[nt][3] * i1));
            *(uint2*)&row[nt * 8 + 2 * t] = r;
        }
    }
}

// ============================================================================
extern "C" void kernel_launch(void* const* d_in, const int* in_sizes, int n_in,
                              void* d_out, int out_size)
{
    const float* x  = (const float*)d_in[0];
    const float* Wq = (const float*)d_in[1];
    const float* bq = (const float*)d_in[2];
    const float* Wk = (const float*)d_in[3];
    const float* bk = (const float*)d_in[4];
    const float* Wv = (const float*)d_in[5];
    const float* bv = (const float*)d_in[6];
    const float* Wp = (const float*)d_in[7];
    const float* bp = (const float*)d_in[8];
    float* out = (float*)d_out;

    cudaFuncSetAttribute(gemm_tf32, cudaFuncAttributeMaxDynamicSharedMemorySize,
                         GEMM_SMEM);
    cudaFuncSetAttribute(attn_mma, cudaFuncAttributeMaxDynamicSharedMemorySize,
                         ATTN_SMEM);

    float *xr, *wr;
    cudaGetSymbolAddress((void**)&xr, g_xr);
    cudaGetSymbolAddress((void**)&wr, g_wr);

    // pre-round all operands to tf32 (one launch)
    round_all<<<MTOT * DD / 4 / 256 + 4 * DD * DD / 4 / 256, 256>>>(
        x, Wq, Wk, Wv, Wp, xr, wr);

    // fused QKV projection: grid (24, 49), BN=128
    gemm_tf32<<<dim3(24, MTOT / 128), 256, GEMM_SMEM>>>(bq, bk, bv, nullptr);

    dim3 ga((SS + 127) / 128, HH, BB);  // 13 x 16 x 4
    attn_mma<<<ga, 256, ATTN_SMEM>>>();

    // output projection: grid (8, 49)
    gemm_tf32<<<dim3(8, MTOT / 128), 256, GEMM_SMEM>>>(bp, bp, bp, out);
}